// round 7
// baseline (speedup 1.0000x reference)
#include <cuda_runtime.h>
#include <cuda_bf16.h>
#include <cstddef>
#include <cstdint>

#define N_LIT 200000
#define N_CLS 800000
#define NE    2400000
#define NT    (N_CLS + N_LIT)
#define CH    64
#define NVAR  (N_LIT/2)
#define NLAY  4
#define SCAN_B 1024

typedef unsigned long long u64;

// ---------------- device scratch (static, no allocation) ----------------
__device__ float g_hlA[(size_t)N_LIT * CH];
__device__ float g_hlB[(size_t)N_LIT * CH];
__device__ float g_hc [(size_t)N_CLS * CH];
__device__ float g_m  [(size_t)N_CLS * CH];
__device__ int   g_cnt[NT];          // zero-init; re-zeroed by fill_kernel each call
__device__ float g_inv[NT];
__device__ int   g_rs [NT + 1];
__device__ int   g_cur[NT];
__device__ int   g_adj[2 * NE];      // [0,NE): lits by clause; [NE,2NE): clauses by literal
__device__ u64   g_tiles[1024];      // decoupled-lookback state: (flag<<32)|value
__device__ unsigned int g_ctr;       // ticket counter

__device__ __forceinline__ float silu(float x) { return x / (1.0f + __expf(-x)); }

// ---- f32x2 packed helpers (FFMA2 path, sm_100+) ----
__device__ __forceinline__ u64 pack2(float lo, float hi) {
    u64 r; asm("mov.b64 %0, {%1,%2};" : "=l"(r) : "f"(lo), "f"(hi)); return r;
}
__device__ __forceinline__ u64 pack_dup(float x) {
    u64 r; asm("mov.b64 %0, {%1,%1};" : "=l"(r) : "f"(x)); return r;
}
__device__ __forceinline__ void fma2(u64& acc, u64 a, u64 b) {
    asm("fma.rn.f32x2 %0, %1, %2, %0;" : "+l"(acc) : "l"(a), "l"(b));
}
__device__ __forceinline__ float2 unpack2(u64 v) {
    float2 f; asm("mov.b64 {%0,%1}, %2;" : "=f"(f.x), "=f"(f.y) : "l"(v)); return f;
}
__device__ __forceinline__ void lds_v2u64(u64& a, u64& b, uint32_t addr) {
    asm("ld.shared.v2.b64 {%0,%1}, [%2];" : "=l"(a), "=l"(b) : "r"(addr));
}

// acc2[32] += x_row[0..63] (gmem, LDG.128) @ W_block (smem byte addr sw, row-major 64 wide)
__device__ __forceinline__ void gemm_v(u64* acc2, const float* __restrict__ x, uint32_t sw)
{
    #pragma unroll
    for (int kk = 0; kk < 4; kk++) {
        float4 xv0 = __ldg((const float4*)x + kk * 4 + 0);
        float4 xv1 = __ldg((const float4*)x + kk * 4 + 1);
        float4 xv2 = __ldg((const float4*)x + kk * 4 + 2);
        float4 xv3 = __ldg((const float4*)x + kk * 4 + 3);
        float xs[16] = {xv0.x, xv0.y, xv0.z, xv0.w,
                        xv1.x, xv1.y, xv1.z, xv1.w,
                        xv2.x, xv2.y, xv2.z, xv2.w,
                        xv3.x, xv3.y, xv3.z, xv3.w};
        #pragma unroll
        for (int e = 0; e < 16; e++) {
            u64 xk2 = pack_dup(xs[e]);
            uint32_t ra = sw + ((kk * 16 + e) << 8);
            #pragma unroll
            for (int j = 0; j < 16; j++) {
                u64 w0, w1;
                lds_v2u64(w0, w1, ra + (j << 4));
                fma2(acc2[2 * j],     xk2, w0);
                fma2(acc2[2 * j + 1], xk2, w1);
            }
        }
    }
}

// ---------------- 1) encoder + edge counting (fused) ----------------
__global__ void __launch_bounds__(128) encoder_kernel(
    const float* __restrict__ xl, const float* __restrict__ xc,
    const float* __restrict__ w1, const float* __restrict__ b1,
    const float* __restrict__ w2, const float* __restrict__ b2,
    const int* __restrict__ el, const int* __restrict__ ec,
    int* __restrict__ cnt,
    float* __restrict__ hl, float* __restrict__ hc)
{
    __shared__ __align__(16) float sW1[4 * CH];
    __shared__ __align__(16) float sb1[CH];
    __shared__ __align__(16) float sW2[CH * CH];
    __shared__ __align__(16) float sb2[CH];
    for (int t = threadIdx.x; t < 64; t += 128) ((float4*)sW1)[t] = ((const float4*)w1)[t];
    for (int t = threadIdx.x; t < CH * 16; t += 128) ((float4*)sW2)[t] = ((const float4*)w2)[t];
    if (threadIdx.x < CH) { sb1[threadIdx.x] = b1[threadIdx.x]; sb2[threadIdx.x] = b2[threadIdx.x]; }
    __syncthreads();
    uint32_t sw2a = (uint32_t)__cvta_generic_to_shared(sW2);

    int i = blockIdx.x * 128 + threadIdx.x;
    int stride = gridDim.x * 128;

    for (size_t e = i; e < NE; e += stride) {
        atomicAdd(cnt + __ldg(ec + e), 1);
        atomicAdd(cnt + N_CLS + __ldg(el + e), 1);
    }

    if (i >= NT) return;
    const float* x;
    float* out;
    if (i < N_LIT) { x = xl + (size_t)i * 4;           out = hl + (size_t)i * CH; }
    else           { x = xc + (size_t)(i - N_LIT) * 4; out = hc + (size_t)(i - N_LIT) * CH; }
    float4 xv = __ldg((const float4*)x);

    u64 acc2[32];
    #pragma unroll
    for (int j = 0; j < 16; j++) {
        float4 bv = ((const float4*)sb2)[j];
        acc2[2 * j]     = pack2(bv.x, bv.y);
        acc2[2 * j + 1] = pack2(bv.z, bv.w);
    }

    #pragma unroll 8
    for (int k = 0; k < CH; k++) {
        float t = sb1[k] + xv.x * sW1[k] + xv.y * sW1[CH + k] + xv.z * sW1[2 * CH + k] + xv.w * sW1[3 * CH + k];
        u64 s2 = pack_dup(silu(t));
        uint32_t ra = sw2a + (k << 8);
        #pragma unroll
        for (int j = 0; j < 16; j++) {
            u64 w0, w1v;
            lds_v2u64(w0, w1v, ra + (j << 4));
            fma2(acc2[2 * j],     s2, w0);
            fma2(acc2[2 * j + 1], s2, w1v);
        }
    }
    #pragma unroll
    for (int j = 0; j < 16; j++) {
        float2 a = unpack2(acc2[2 * j]);
        float2 b = unpack2(acc2[2 * j + 1]);
        ((float4*)out)[j] = make_float4(a.x, a.y, b.x, b.y);
    }
}

// ---------------- 2) single-pass scan (decoupled lookback, ticket-ordered) ----------------
__global__ void __launch_bounds__(SCAN_B) scan_onepass(
    const int* __restrict__ cnt, int* __restrict__ rs, int* __restrict__ cur,
    float* __restrict__ inv, int n)
{
    __shared__ int s[SCAN_B];
    __shared__ int sbid;
    __shared__ int sbase;
    if (threadIdx.x == 0) sbid = (int)atomicAdd(&g_ctr, 1u);
    __syncthreads();
    int bid = sbid;
    int i = bid * SCAN_B + threadIdx.x;
    int v = (i < n) ? cnt[i] : 0;
    s[threadIdx.x] = v;
    __syncthreads();
    for (int off = 1; off < SCAN_B; off <<= 1) {
        int t = (threadIdx.x >= off) ? s[threadIdx.x - off] : 0;
        __syncthreads();
        s[threadIdx.x] += t;
        __syncthreads();
    }
    if (threadIdx.x == 0) {
        int total = s[SCAN_B - 1];
        if (bid == 0) {
            atomicExch(&g_tiles[0], (2ull << 32) | (unsigned)total);
            sbase = 0;
        } else {
            atomicExch(&g_tiles[bid], (1ull << 32) | (unsigned)total);
            int base = 0;
            int t = bid - 1;
            while (t >= 0) {
                u64 st;
                do { st = atomicAdd(&g_tiles[t], 0ull); } while ((st >> 32) == 0ull);
                base += (int)(unsigned)st;
                if ((st >> 32) == 2ull) break;
                t--;
            }
            atomicExch(&g_tiles[bid], (2ull << 32) | (unsigned)(base + total));
            sbase = base;
        }
    }
    __syncthreads();
    int base = sbase;
    if (i < n) {
        int r = base + s[threadIdx.x] - v;
        rs[i] = r;
        cur[i] = r;
        inv[i] = (v > 0) ? (1.0f / (float)v) : 1.0f;
    }
    if (bid == 0 && threadIdx.x == 0) rs[n] = 2 * NE;
}

// ---------------- 3) adjacency fill (+ reset cnt / scan state for next call) ----------------
__global__ void fill_kernel(const int* __restrict__ el, const int* __restrict__ ec,
                            int* __restrict__ cur, int* __restrict__ adj,
                            int* __restrict__ cnt) {
    int e = blockIdx.x * 256 + threadIdx.x;
    if (e < NT) cnt[e] = 0;
    if (e < 1024) g_tiles[e] = 0ull;
    if (e == 0) g_ctr = 0u;
    if (e < NE) {
        int l = __ldg(el + e), c = __ldg(ec + e);
        adj[atomicAdd(cur + c, 1)]         = l;
        adj[atomicAdd(cur + N_CLS + l, 1)] = c;
    }
}

// ---------------- aggregation: 8 lanes per node (4 nodes/warp), high MLP ----------------
__global__ void __launch_bounds__(256) agg_kernel(
    const float* __restrict__ src, const int* __restrict__ rs,
    const int* __restrict__ adj, const float* __restrict__ inv,
    float* __restrict__ m, int n)
{
    int w = (blockIdx.x * 256 + threadIdx.x) >> 5;   // global warp id
    int lane = threadIdx.x & 31;
    int sub = lane >> 3;         // 0..3: node slot within warp
    int li  = lane & 7;          // 0..7: lane within node group
    int node = w * 4 + sub;
    if (node >= n) node = n - 1;            // clamp: redundant identical work, keeps warp full
    if (w * 4 >= n) return;                 // whole warp out of range

    int start = __ldg(rs + node), end = __ldg(rs + node + 1);
    const char* basep = (const char*)src;
    float4 a0 = make_float4(0.f, 0.f, 0.f, 0.f);
    float4 a1 = make_float4(0.f, 0.f, 0.f, 0.f);

    for (int p0 = start; p0 < end; p0 += 8) {
        int idx = p0 + li;
        int aj = (idx < end) ? __ldg(adj + idx) : 0;
        int mc = min(8, end - p0);
        for (int t = 0; t < mc; t++) {
            int j = __shfl_sync(0xffffffffu, aj, t, 8);   // broadcast within 8-lane group
            const float4* row = (const float4*)(basep + ((size_t)(unsigned)j << 8));
            float4 v0 = __ldg(row + li);
            float4 v1 = __ldg(row + li + 8);
            a0.x += v0.x; a0.y += v0.y; a0.z += v0.z; a0.w += v0.w;
            a1.x += v1.x; a1.y += v1.y; a1.z += v1.z; a1.w += v1.w;
        }
    }
    float iv = __ldg(inv + node);
    float4 o0 = make_float4(a0.x * iv, a0.y * iv, a0.z * iv, a0.w * iv);
    float4 o1 = make_float4(a1.x * iv, a1.y * iv, a1.z * iv, a1.w * iv);
    float4* out = (float4*)(m + (size_t)node * CH);
    out[li]     = o0;
    out[li + 8] = o1;
}

// ---------------- cls update: hc = silu([hc, m] @ Wc + bc) in place ----------------
__global__ void __launch_bounds__(128) cls_update(
    float* __restrict__ hc, const float* __restrict__ m,
    const float* __restrict__ W, const float* __restrict__ b)
{
    __shared__ __align__(16) float sW[2 * CH * CH];
    __shared__ __align__(16) float sb[CH];
    for (int t = threadIdx.x; t < 2 * CH * 16; t += 128) ((float4*)sW)[t] = ((const float4*)W)[t];
    if (threadIdx.x < CH) sb[threadIdx.x] = b[threadIdx.x];
    __syncthreads();
    uint32_t swa = (uint32_t)__cvta_generic_to_shared(sW);

    size_t i = (size_t)blockIdx.x * 128 + threadIdx.x;
    if (i >= N_CLS) return;

    u64 acc2[32];
    #pragma unroll
    for (int j = 0; j < 16; j++) {
        float4 bv = ((const float4*)sb)[j];
        acc2[2 * j]     = pack2(bv.x, bv.y);
        acc2[2 * j + 1] = pack2(bv.z, bv.w);
    }

    gemm_v(acc2, hc + i * CH, swa);
    gemm_v(acc2, m  + i * CH, swa + CH * CH * 4);

    float* row = hc + i * CH;
    #pragma unroll
    for (int j = 0; j < 16; j++) {
        float2 a = unpack2(acc2[2 * j]);
        float2 c = unpack2(acc2[2 * j + 1]);
        ((float4*)row)[j] = make_float4(silu(a.x), silu(a.y), silu(c.x), silu(c.y));
    }
}

// ---------------- lit update: hdst = silu([hsrc, m, hsrc_flip] @ Wl + bl) ----------------
__global__ void __launch_bounds__(128) lit_update(
    const float* __restrict__ hsrc, float* __restrict__ hdst,
    const float* __restrict__ m,
    const float* __restrict__ W, const float* __restrict__ b)
{
    extern __shared__ __align__(16) float smem[];
    float* sW = smem;                    // 192*64 floats = 48KB
    float* sb = smem + 3 * CH * CH;
    for (int t = threadIdx.x; t < 3 * CH * 16; t += 128) ((float4*)sW)[t] = ((const float4*)W)[t];
    if (threadIdx.x < CH) sb[threadIdx.x] = b[threadIdx.x];
    __syncthreads();
    uint32_t swa = (uint32_t)__cvta_generic_to_shared(sW);

    size_t i = (size_t)blockIdx.x * 128 + threadIdx.x;
    if (i >= N_LIT) return;

    u64 acc2[32];
    #pragma unroll
    for (int j = 0; j < 16; j++) {
        float4 bv = ((const float4*)sb)[j];
        acc2[2 * j]     = pack2(bv.x, bv.y);
        acc2[2 * j + 1] = pack2(bv.z, bv.w);
    }

    gemm_v(acc2, hsrc + i * CH,       swa);
    gemm_v(acc2, m    + i * CH,       swa + CH * CH * 4);
    gemm_v(acc2, hsrc + (i ^ 1) * CH, swa + 2 * CH * CH * 4);

    float* out = hdst + i * CH;
    #pragma unroll
    for (int j = 0; j < 16; j++) {
        float2 a = unpack2(acc2[2 * j]);
        float2 c = unpack2(acc2[2 * j + 1]);
        ((float4*)out)[j] = make_float4(silu(a.x), silu(a.y), silu(c.x), silu(c.y));
    }
}

// ---------------- readout ----------------
#define W1T_STRIDE 132   // floats; 528B, 16B-aligned
__global__ void __launch_bounds__(128) readout_kernel(
    const float* __restrict__ hl,
    const float* __restrict__ w1, const float* __restrict__ b1,
    const float* __restrict__ w2, const float* __restrict__ b2,
    float* __restrict__ out)
{
    extern __shared__ __align__(16) float smem[];
    float* sW1T = smem;                       // [128][132] transposed, padded
    float* sb1  = smem + 128 * W1T_STRIDE;
    float* sW2  = sb1 + 128;
    float* sb2  = sW2 + 256;
    for (int t = threadIdx.x; t < 128 * 128; t += 128) {
        int i = t >> 7, k = t & 127;
        sW1T[k * W1T_STRIDE + i] = w1[t];     // w1[i][k]
    }
    sb1[threadIdx.x] = b1[threadIdx.x];
    for (int t = threadIdx.x; t < 256; t += 128) sW2[t] = w2[t];
    if (threadIdx.x < 2) sb2[threadIdx.x] = b2[threadIdx.x];
    __syncthreads();
    uint32_t swa = (uint32_t)__cvta_generic_to_shared(sW1T);

    int v = blockIdx.x * 128 + threadIdx.x;
    if (v >= NVAR) return;

    u64 hv2[64];
    const float4* hp = (const float4*)(hl + (size_t)v * 128);
    #pragma unroll
    for (int j = 0; j < 32; j++) {
        float4 h = __ldg(hp + j);
        hv2[2 * j]     = pack2(h.x, h.y);
        hv2[2 * j + 1] = pack2(h.z, h.w);
    }

    float y0 = sb2[0], y1 = sb2[1];
    #pragma unroll 2
    for (int k = 0; k < 128; k++) {
        u64 t0 = 0, t1 = 0, t2 = 0, t3 = 0;
        uint32_t ra = swa + k * (W1T_STRIDE * 4);
        #pragma unroll
        for (int j = 0; j < 32; j++) {
            u64 w0, w1v;
            lds_v2u64(w0, w1v, ra + (j << 4));
            fma2((j & 1) ? t1 : t0, hv2[2 * j],     w0);
            fma2((j & 1) ? t3 : t2, hv2[2 * j + 1], w1v);
        }
        float2 a = unpack2(t0), bq = unpack2(t1), c = unpack2(t2), d = unpack2(t3);
        float t = ((a.x + a.y) + (bq.x + bq.y)) + ((c.x + c.y) + (d.x + d.y)) + sb1[k];
        float s = silu(t);
        y0 += s * sW2[2 * k];
        y1 += s * sW2[2 * k + 1];
    }
    out[2 * v]     = y0;
    out[2 * v + 1] = y1;
}

// ---------------- launcher ----------------
extern "C" void kernel_launch(void* const* d_in, const int* in_sizes, int n_in,
                              void* d_out, int out_size)
{
    const float* x_lit  = (const float*)d_in[0];
    const float* x_cls  = (const float*)d_in[1];
    const int*   e_lit  = (const int*)  d_in[2];
    const int*   e_cls  = (const int*)  d_in[3];
    const float* enc_w1 = (const float*)d_in[4];
    const float* enc_b1 = (const float*)d_in[5];
    const float* enc_w2 = (const float*)d_in[6];
    const float* enc_b2 = (const float*)d_in[7];
    const float* Wc     = (const float*)d_in[8];
    const float* bc     = (const float*)d_in[9];
    const float* Wl     = (const float*)d_in[10];
    const float* bl     = (const float*)d_in[11];
    const float* out_w1 = (const float*)d_in[12];
    const float* out_b1 = (const float*)d_in[13];
    const float* out_w2 = (const float*)d_in[14];
    const float* out_b2 = (const float*)d_in[15];
    float* y = (float*)d_out;

    float *p_hlA, *p_hlB, *p_hc, *p_m, *p_inv;
    int *p_cnt, *p_rs, *p_cur, *p_adj;
    cudaGetSymbolAddress((void**)&p_hlA, g_hlA);
    cudaGetSymbolAddress((void**)&p_hlB, g_hlB);
    cudaGetSymbolAddress((void**)&p_hc,  g_hc);
    cudaGetSymbolAddress((void**)&p_m,   g_m);
    cudaGetSymbolAddress((void**)&p_cnt, g_cnt);
    cudaGetSymbolAddress((void**)&p_inv, g_inv);
    cudaGetSymbolAddress((void**)&p_rs,  g_rs);
    cudaGetSymbolAddress((void**)&p_cur, g_cur);
    cudaGetSymbolAddress((void**)&p_adj, g_adj);

    cudaFuncSetAttribute(lit_update, cudaFuncAttributeMaxDynamicSharedMemorySize,
                         (3 * CH * CH + CH) * 4);
    cudaFuncSetAttribute(readout_kernel, cudaFuncAttributeMaxDynamicSharedMemorySize,
                         (128 * W1T_STRIDE + 128 + 256 + 8) * 4);

    // 1) encoder + edge counting (cnt/tiles/ctr reset by previous call's fill / static init)
    encoder_kernel<<<(NT + 127) / 128, 128>>>(
        x_lit, x_cls, enc_w1, enc_b1, enc_w2, enc_b2,
        e_lit, e_cls, p_cnt, p_hlA, p_hc);

    // 2) single-pass scan -> rs, cur, inv
    int nb = (NT + SCAN_B - 1) / SCAN_B;   // 977
    scan_onepass<<<nb, SCAN_B>>>(p_cnt, p_rs, p_cur, p_inv, NT);

    // 3) adjacency fill + reset cnt/scan state
    fill_kernel<<<(NE + 255) / 256, 256>>>(e_lit, e_cls, p_cur, p_adj, p_cnt);

    // 4+) message-passing layers (agg_cls is kernel launch #4 -> ncu profile slot)
    const int wc = (N_CLS + 3) / 4;                 // warps for cls agg
    const int wl = (N_LIT + 3) / 4;                 // warps for lit agg
    float* cur = p_hlA;
    float* nxt = p_hlB;
    for (int l = 0; l < NLAY; l++) {
        agg_kernel<<<(wc * 32 + 255) / 256, 256>>>(
            cur, p_rs, p_adj, p_inv, p_m, N_CLS);
        cls_update<<<(N_CLS + 127) / 128, 128>>>(
            p_hc, p_m, Wc + (size_t)l * 2 * CH * CH, bc + l * CH);
        agg_kernel<<<(wl * 32 + 255) / 256, 256>>>(
            p_hc, p_rs + N_CLS, p_adj, p_inv + N_CLS, p_m, N_LIT);
        lit_update<<<(N_LIT + 127) / 128, 128, (3 * CH * CH + CH) * 4>>>(
            cur, nxt, p_m, Wl + (size_t)l * 3 * CH * CH, bl + l * CH);
        float* tmp = cur; cur = nxt; nxt = tmp;
    }

    // readout
    readout_kernel<<<(NVAR + 127) / 128, 128, (128 * W1T_STRIDE + 128 + 256 + 8) * 4>>>(
        cur, out_w1, out_b1, out_w2, out_b2, y);
}

// round 8
// speedup vs baseline: 1.0688x; 1.0688x over previous
#include <cuda_runtime.h>
#include <cuda_bf16.h>
#include <cstddef>
#include <cstdint>

#define N_LIT 200000
#define N_CLS 800000
#define NE    2400000
#define NT    (N_CLS + N_LIT)
#define CH    64
#define NVAR  (N_LIT/2)
#define NLAY  4
#define SCAN_B 1024

typedef unsigned long long u64;

// ---------------- device scratch (static, no allocation) ----------------
__device__ float g_hlA[(size_t)N_LIT * CH];
__device__ float g_hlB[(size_t)N_LIT * CH];
__device__ float g_hc [(size_t)N_CLS * CH];
__device__ float g_m  [(size_t)N_CLS * CH];
__device__ int   g_cnt[NT];          // zero-init; re-zeroed by fill_kernel each call
__device__ float g_inv[NT];
__device__ int   g_rs [NT + 1];
__device__ int   g_cur[NT];
__device__ int   g_adj[2 * NE];      // [0,NE): lits by clause; [NE,2NE): clauses by literal
__device__ u64   g_tiles[1024];      // decoupled-lookback state: (flag<<32)|value
__device__ unsigned int g_ctr;       // ticket counter

__device__ __forceinline__ float silu(float x) { return x / (1.0f + __expf(-x)); }

// ---- f32x2 packed helpers (encoder/readout scalar path) ----
__device__ __forceinline__ u64 pack2(float lo, float hi) {
    u64 r; asm("mov.b64 %0, {%1,%2};" : "=l"(r) : "f"(lo), "f"(hi)); return r;
}
__device__ __forceinline__ u64 pack_dup(float x) {
    u64 r; asm("mov.b64 %0, {%1,%1};" : "=l"(r) : "f"(x)); return r;
}
__device__ __forceinline__ void fma2(u64& acc, u64 a, u64 b) {
    asm("fma.rn.f32x2 %0, %1, %2, %0;" : "+l"(acc) : "l"(a), "l"(b));
}
__device__ __forceinline__ float2 unpack2(u64 v) {
    float2 f; asm("mov.b64 {%0,%1}, %2;" : "=f"(f.x), "=f"(f.y) : "l"(v)); return f;
}
__device__ __forceinline__ void lds_v2u64(u64& a, u64& b, uint32_t addr) {
    asm("ld.shared.v2.b64 {%0,%1}, [%2];" : "=l"(a), "=l"(b) : "r"(addr));
}

// ---- bf16 split-pack: x = hi + lo (each bf16), packed as bf16x2 pairs along k ----
__device__ __forceinline__ void split2(float x0, float x1, uint32_t& hi, uint32_t& lo) {
    __nv_bfloat16 h0 = __float2bfloat16_rn(x0);
    __nv_bfloat16 h1 = __float2bfloat16_rn(x1);
    float r0 = x0 - __bfloat162float(h0);
    float r1 = x1 - __bfloat162float(h1);
    __nv_bfloat16 l0 = __float2bfloat16_rn(r0);
    __nv_bfloat16 l1 = __float2bfloat16_rn(r1);
    hi = ((uint32_t)__bfloat16_as_ushort(h1) << 16) | (uint32_t)__bfloat16_as_ushort(h0);
    lo = ((uint32_t)__bfloat16_as_ushort(l1) << 16) | (uint32_t)__bfloat16_as_ushort(l0);
}

// bf16 m16n8k16 MMA, fp32 accumulate
__device__ __forceinline__ void mma16816(float* c,
    uint32_t a0, uint32_t a1, uint32_t a2, uint32_t a3, uint32_t b0, uint32_t b1)
{
    asm("mma.sync.aligned.m16n8k16.row.col.f32.bf16.bf16.f32 "
        "{%0,%1,%2,%3}, {%4,%5,%6,%7}, {%8,%9}, {%0,%1,%2,%3};"
        : "+f"(c[0]), "+f"(c[1]), "+f"(c[2]), "+f"(c[3])
        : "r"(a0), "r"(a1), "r"(a2), "r"(a3), "r"(b0), "r"(b1));
}

// ---------------- 1) encoder + edge counting (fused) ----------------
__global__ void __launch_bounds__(128) encoder_kernel(
    const float* __restrict__ xl, const float* __restrict__ xc,
    const float* __restrict__ w1, const float* __restrict__ b1,
    const float* __restrict__ w2, const float* __restrict__ b2,
    const int* __restrict__ el, const int* __restrict__ ec,
    int* __restrict__ cnt,
    float* __restrict__ hl, float* __restrict__ hc)
{
    __shared__ __align__(16) float sW1[4 * CH];
    __shared__ __align__(16) float sb1[CH];
    __shared__ __align__(16) float sW2[CH * CH];
    __shared__ __align__(16) float sb2[CH];
    for (int t = threadIdx.x; t < 64; t += 128) ((float4*)sW1)[t] = ((const float4*)w1)[t];
    for (int t = threadIdx.x; t < CH * 16; t += 128) ((float4*)sW2)[t] = ((const float4*)w2)[t];
    if (threadIdx.x < CH) { sb1[threadIdx.x] = b1[threadIdx.x]; sb2[threadIdx.x] = b2[threadIdx.x]; }
    __syncthreads();
    uint32_t sw2a = (uint32_t)__cvta_generic_to_shared(sW2);

    int i = blockIdx.x * 128 + threadIdx.x;
    int stride = gridDim.x * 128;

    for (size_t e = i; e < NE; e += stride) {
        atomicAdd(cnt + __ldg(ec + e), 1);
        atomicAdd(cnt + N_CLS + __ldg(el + e), 1);
    }

    if (i >= NT) return;
    const float* x;
    float* out;
    if (i < N_LIT) { x = xl + (size_t)i * 4;           out = hl + (size_t)i * CH; }
    else           { x = xc + (size_t)(i - N_LIT) * 4; out = hc + (size_t)(i - N_LIT) * CH; }
    float4 xv = __ldg((const float4*)x);

    u64 acc2[32];
    #pragma unroll
    for (int j = 0; j < 16; j++) {
        float4 bv = ((const float4*)sb2)[j];
        acc2[2 * j]     = pack2(bv.x, bv.y);
        acc2[2 * j + 1] = pack2(bv.z, bv.w);
    }

    #pragma unroll 8
    for (int k = 0; k < CH; k++) {
        float t = sb1[k] + xv.x * sW1[k] + xv.y * sW1[CH + k] + xv.z * sW1[2 * CH + k] + xv.w * sW1[3 * CH + k];
        u64 s2 = pack_dup(silu(t));
        uint32_t ra = sw2a + (k << 8);
        #pragma unroll
        for (int j = 0; j < 16; j++) {
            u64 w0, w1v;
            lds_v2u64(w0, w1v, ra + (j << 4));
            fma2(acc2[2 * j],     s2, w0);
            fma2(acc2[2 * j + 1], s2, w1v);
        }
    }
    #pragma unroll
    for (int j = 0; j < 16; j++) {
        float2 a = unpack2(acc2[2 * j]);
        float2 b = unpack2(acc2[2 * j + 1]);
        ((float4*)out)[j] = make_float4(a.x, a.y, b.x, b.y);
    }
}

// ---------------- 2) single-pass scan (decoupled lookback, ticket-ordered) ----------------
__global__ void __launch_bounds__(SCAN_B) scan_onepass(
    const int* __restrict__ cnt, int* __restrict__ rs, int* __restrict__ cur,
    float* __restrict__ inv, int n)
{
    __shared__ int s[SCAN_B];
    __shared__ int sbid;
    __shared__ int sbase;
    if (threadIdx.x == 0) sbid = (int)atomicAdd(&g_ctr, 1u);
    __syncthreads();
    int bid = sbid;
    int i = bid * SCAN_B + threadIdx.x;
    int v = (i < n) ? cnt[i] : 0;
    s[threadIdx.x] = v;
    __syncthreads();
    for (int off = 1; off < SCAN_B; off <<= 1) {
        int t = (threadIdx.x >= off) ? s[threadIdx.x - off] : 0;
        __syncthreads();
        s[threadIdx.x] += t;
        __syncthreads();
    }
    if (threadIdx.x == 0) {
        int total = s[SCAN_B - 1];
        if (bid == 0) {
            atomicExch(&g_tiles[0], (2ull << 32) | (unsigned)total);
            sbase = 0;
        } else {
            atomicExch(&g_tiles[bid], (1ull << 32) | (unsigned)total);
            int base = 0;
            int t = bid - 1;
            while (t >= 0) {
                u64 st;
                do { st = atomicAdd(&g_tiles[t], 0ull); } while ((st >> 32) == 0ull);
                base += (int)(unsigned)st;
                if ((st >> 32) == 2ull) break;
                t--;
            }
            atomicExch(&g_tiles[bid], (2ull << 32) | (unsigned)(base + total));
            sbase = base;
        }
    }
    __syncthreads();
    int base = sbase;
    if (i < n) {
        int r = base + s[threadIdx.x] - v;
        rs[i] = r;
        cur[i] = r;
        inv[i] = (v > 0) ? (1.0f / (float)v) : 1.0f;
    }
    if (bid == 0 && threadIdx.x == 0) rs[n] = 2 * NE;
}

// ---------------- 3) adjacency fill (+ reset cnt / scan state for next call) ----------------
__global__ void fill_kernel(const int* __restrict__ el, const int* __restrict__ ec,
                            int* __restrict__ cur, int* __restrict__ adj,
                            int* __restrict__ cnt) {
    int e = blockIdx.x * 256 + threadIdx.x;
    if (e < NT) cnt[e] = 0;
    if (e < 1024) g_tiles[e] = 0ull;
    if (e == 0) g_ctr = 0u;
    if (e < NE) {
        int l = __ldg(el + e), c = __ldg(ec + e);
        adj[atomicAdd(cur + c, 1)]         = l;
        adj[atomicAdd(cur + N_CLS + l, 1)] = c;
    }
}

// ---------------- aggregation: warp-per-node gather, MLP=4 (round-3 form) ----------------
__global__ void __launch_bounds__(256) agg_kernel(
    const float* __restrict__ src, const int* __restrict__ rs,
    const int* __restrict__ adj, const float* __restrict__ inv,
    float* __restrict__ m, int n)
{
    int w = (blockIdx.x * 256 + threadIdx.x) >> 5;
    if (w >= n) return;
    int lane = threadIdx.x & 31;
    int start = __ldg(rs + w), end = __ldg(rs + w + 1);
    const float2* base = (const float2*)src;
    float ax = 0.f, ay = 0.f;
    int p = start;
    for (; p + 4 <= end; p += 4) {
        int j0 = __ldg(adj + p),     j1 = __ldg(adj + p + 1);
        int j2 = __ldg(adj + p + 2), j3 = __ldg(adj + p + 3);
        float2 v0 = __ldg(base + (size_t)j0 * 32 + lane);
        float2 v1 = __ldg(base + (size_t)j1 * 32 + lane);
        float2 v2 = __ldg(base + (size_t)j2 * 32 + lane);
        float2 v3 = __ldg(base + (size_t)j3 * 32 + lane);
        ax += (v0.x + v1.x) + (v2.x + v3.x);
        ay += (v0.y + v1.y) + (v2.y + v3.y);
    }
    for (; p < end; p++) {
        int j = __ldg(adj + p);
        float2 v = __ldg(base + (size_t)j * 32 + lane);
        ax += v.x; ay += v.y;
    }
    float iv = __ldg(inv + w);
    ((float2*)m)[(size_t)w * 32 + lane] = make_float2(ax * iv, ay * iv);
}

// ================= HMMA update kernels =================
// Block: 128 threads (4 warps), 64 nodes. Warp w handles local rows w*16..w*16+15.
// A (concat features) split bf16 hi/lo in smem, stride 68 u32 (conflict-free).
// W split bf16 hi/lo, packed k-pairs, stride 72 u32 (conflict-free).
// D = Ah@Bh + Ah@Bl + Al@Bh  (AlBl dropped, ~2^-18)

#define AST 68
#define WST 72

// ---- cls: hc = silu([hc, m] @ Wc + bc), K=128, in place ----
__global__ void __launch_bounds__(128) cls_update(
    float* __restrict__ hc, const float* __restrict__ m,
    const float* __restrict__ W, const float* __restrict__ b)
{
    extern __shared__ uint32_t smu[];
    uint32_t* sAh = smu;                   // 64*68
    uint32_t* sAl = sAh + 64 * AST;
    uint32_t* sWh = sAl + 64 * AST;        // 64*72
    uint32_t* sWl = sWh + 64 * WST;
    float*    sb  = (float*)(sWl + 64 * WST);

    int tid = threadIdx.x;
    size_t gbase = (size_t)blockIdx.x * 64;

    // stage W (64 k-pairs x 64 cols), split hi/lo
    for (int idx = tid; idx < 64 * 64; idx += 128) {
        int p = idx >> 6, c = idx & 63;
        float w0 = __ldg(W + (size_t)(2 * p) * 64 + c);
        float w1 = __ldg(W + (size_t)(2 * p + 1) * 64 + c);
        uint32_t hi, lo; split2(w0, w1, hi, lo);
        sWh[p * WST + c] = hi; sWl[p * WST + c] = lo;
    }
    // stage A: self (pairs 0..31) + m (pairs 32..63)
    for (int idx = tid; idx < 64 * 32; idx += 128) {
        int nd = idx >> 5, pj = idx & 31;
        float2 v = __ldg((const float2*)(hc + (gbase + nd) * CH) + pj);
        uint32_t hi, lo; split2(v.x, v.y, hi, lo);
        sAh[nd * AST + pj] = hi; sAl[nd * AST + pj] = lo;
        float2 vm = __ldg((const float2*)(m + (gbase + nd) * CH) + pj);
        split2(vm.x, vm.y, hi, lo);
        sAh[nd * AST + 32 + pj] = hi; sAl[nd * AST + 32 + pj] = lo;
    }
    if (tid < 64) sb[tid] = b[tid];
    __syncthreads();

    int lane = tid & 31, warp = tid >> 5;
    int g = lane >> 2, t4 = lane & 3;
    int r0 = warp * 16 + g;

    float c[8][4];
    #pragma unroll
    for (int nt = 0; nt < 8; nt++) { c[nt][0] = c[nt][1] = c[nt][2] = c[nt][3] = 0.f; }

    #pragma unroll
    for (int s = 0; s < 8; s++) {
        int pb = s * 8 + t4;
        uint32_t ah0 = sAh[r0 * AST + pb],       ah1 = sAh[(r0 + 8) * AST + pb];
        uint32_t ah2 = sAh[r0 * AST + pb + 4],   ah3 = sAh[(r0 + 8) * AST + pb + 4];
        uint32_t al0 = sAl[r0 * AST + pb],       al1 = sAl[(r0 + 8) * AST + pb];
        uint32_t al2 = sAl[r0 * AST + pb + 4],   al3 = sAl[(r0 + 8) * AST + pb + 4];
        #pragma unroll
        for (int nt = 0; nt < 8; nt++) {
            int wc = nt * 8 + g;
            uint32_t bh0 = sWh[pb * WST + wc], bh1 = sWh[(pb + 4) * WST + wc];
            uint32_t bl0 = sWl[pb * WST + wc], bl1 = sWl[(pb + 4) * WST + wc];
            mma16816(c[nt], ah0, ah1, ah2, ah3, bh0, bh1);
            mma16816(c[nt], ah0, ah1, ah2, ah3, bl0, bl1);
            mma16816(c[nt], al0, al1, al2, al3, bh0, bh1);
        }
    }

    size_t row0 = gbase + r0, row1 = row0 + 8;
    #pragma unroll
    for (int nt = 0; nt < 8; nt++) {
        int col = nt * 8 + 2 * t4;
        float b0 = sb[col], b1 = sb[col + 1];
        *(float2*)(hc + row0 * CH + col) = make_float2(silu(c[nt][0] + b0), silu(c[nt][1] + b1));
        *(float2*)(hc + row1 * CH + col) = make_float2(silu(c[nt][2] + b0), silu(c[nt][3] + b1));
    }
}

// ---- lit: hdst = silu([hsrc, m, hsrc_flip] @ Wl + bl), K=192 ----
__global__ void __launch_bounds__(128) lit_update(
    const float* __restrict__ hsrc, float* __restrict__ hdst,
    const float* __restrict__ m,
    const float* __restrict__ W, const float* __restrict__ b)
{
    extern __shared__ uint32_t smu[];
    uint32_t* sAh = smu;                   // 64*68 (self pairs 0..31, m pairs 32..63)
    uint32_t* sAl = sAh + 64 * AST;
    uint32_t* sWh = sAl + 64 * AST;        // 96*72
    uint32_t* sWl = sWh + 96 * WST;
    float*    sb  = (float*)(sWl + 96 * WST);

    int tid = threadIdx.x;
    size_t gbase = (size_t)blockIdx.x * 64;

    for (int idx = tid; idx < 96 * 64; idx += 128) {
        int p = idx >> 6, c = idx & 63;
        float w0 = __ldg(W + (size_t)(2 * p) * 64 + c);
        float w1 = __ldg(W + (size_t)(2 * p + 1) * 64 + c);
        uint32_t hi, lo; split2(w0, w1, hi, lo);
        sWh[p * WST + c] = hi; sWl[p * WST + c] = lo;
    }
    for (int idx = tid; idx < 64 * 32; idx += 128) {
        int nd = idx >> 5, pj = idx & 31;
        float2 v = __ldg((const float2*)(hsrc + (gbase + nd) * CH) + pj);
        uint32_t hi, lo; split2(v.x, v.y, hi, lo);
        sAh[nd * AST + pj] = hi; sAl[nd * AST + pj] = lo;
        float2 vm = __ldg((const float2*)(m + (gbase + nd) * CH) + pj);
        split2(vm.x, vm.y, hi, lo);
        sAh[nd * AST + 32 + pj] = hi; sAl[nd * AST + 32 + pj] = lo;
    }
    if (tid < 64) sb[tid] = b[tid];
    __syncthreads();

    int lane = tid & 31, warp = tid >> 5;
    int g = lane >> 2, t4 = lane & 3;
    int r0 = warp * 16 + g;

    float c[8][4];
    #pragma unroll
    for (int nt = 0; nt < 8; nt++) { c[nt][0] = c[nt][1] = c[nt][2] = c[nt][3] = 0.f; }

    // segments 1+2: self + m (A pairs 0..63, W pairs 0..63)
    #pragma unroll
    for (int s = 0; s < 8; s++) {
        int pb = s * 8 + t4;
        uint32_t ah0 = sAh[r0 * AST + pb],       ah1 = sAh[(r0 + 8) * AST + pb];
        uint32_t ah2 = sAh[r0 * AST + pb + 4],   ah3 = sAh[(r0 + 8) * AST + pb + 4];
        uint32_t al0 = sAl[r0 * AST + pb],       al1 = sAl[(r0 + 8) * AST + pb];
        uint32_t al2 = sAl[r0 * AST + pb + 4],   al3 = sAl[(r0 + 8) * AST + pb + 4];
        #pragma unroll
        for (int nt = 0; nt < 8; nt++) {
            int wc = nt * 8 + g;
            uint32_t bh0 = sWh[pb * WST + wc], bh1 = sWh[(pb + 4) * WST + wc];
            uint32_t bl0 = sWl[pb * WST + wc], bl1 = sWl[(pb + 4) * WST + wc];
            mma16816(c[nt], ah0, ah1, ah2, ah3, bh0, bh1);
            mma16816(c[nt], ah0, ah1, ah2, ah3, bl0, bl1);
            mma16816(c[nt], al0, al1, al2, al3, bh0, bh1);
        }
    }
    // segment 3: flip (A = self of node^1, pairs 0..31; W pairs 64..95)
    int f0 = r0 ^ 1, f1 = (r0 + 8) ^ 1;
    #pragma unroll
    for (int s = 0; s < 4; s++) {
        int pa = s * 8 + t4;          // A pair (self region)
        int pw = 64 + s * 8 + t4;     // W pair
        uint32_t ah0 = sAh[f0 * AST + pa],       ah1 = sAh[f1 * AST + pa];
        uint32_t ah2 = sAh[f0 * AST + pa + 4],   ah3 = sAh[f1 * AST + pa + 4];
        uint32_t al0 = sAl[f0 * AST + pa],       al1 = sAl[f1 * AST + pa];
        uint32_t al2 = sAl[f0 * AST + pa + 4],   al3 = sAl[f1 * AST + pa + 4];
        #pragma unroll
        for (int nt = 0; nt < 8; nt++) {
            int wc = nt * 8 + g;
            uint32_t bh0 = sWh[pw * WST + wc], bh1 = sWh[(pw + 4) * WST + wc];
            uint32_t bl0 = sWl[pw * WST + wc], bl1 = sWl[(pw + 4) * WST + wc];
            mma16816(c[nt], ah0, ah1, ah2, ah3, bh0, bh1);
            mma16816(c[nt], ah0, ah1, ah2, ah3, bl0, bl1);
            mma16816(c[nt], al0, al1, al2, al3, bh0, bh1);
        }
    }

    size_t row0 = gbase + r0, row1 = row0 + 8;
    #pragma unroll
    for (int nt = 0; nt < 8; nt++) {
        int col = nt * 8 + 2 * t4;
        float b0 = sb[col], b1 = sb[col + 1];
        *(float2*)(hdst + row0 * CH + col) = make_float2(silu(c[nt][0] + b0), silu(c[nt][1] + b1));
        *(float2*)(hdst + row1 * CH + col) = make_float2(silu(c[nt][2] + b0), silu(c[nt][3] + b1));
    }
}

// ---------------- readout ----------------
#define W1T_STRIDE 132   // floats; 528B, 16B-aligned
__global__ void __launch_bounds__(128) readout_kernel(
    const float* __restrict__ hl,
    const float* __restrict__ w1, const float* __restrict__ b1,
    const float* __restrict__ w2, const float* __restrict__ b2,
    float* __restrict__ out)
{
    extern __shared__ __align__(16) float smem[];
    float* sW1T = smem;                       // [128][132] transposed, padded
    float* sb1  = smem + 128 * W1T_STRIDE;
    float* sW2  = sb1 + 128;
    float* sb2  = sW2 + 256;
    for (int t = threadIdx.x; t < 128 * 128; t += 128) {
        int i = t >> 7, k = t & 127;
        sW1T[k * W1T_STRIDE + i] = w1[t];     // w1[i][k]
    }
    sb1[threadIdx.x] = b1[threadIdx.x];
    for (int t = threadIdx.x; t < 256; t += 128) sW2[t] = w2[t];
    if (threadIdx.x < 2) sb2[threadIdx.x] = b2[threadIdx.x];
    __syncthreads();
    uint32_t swa = (uint32_t)__cvta_generic_to_shared(sW1T);

    int v = blockIdx.x * 128 + threadIdx.x;
    if (v >= NVAR) return;

    u64 hv2[64];
    const float4* hp = (const float4*)(hl + (size_t)v * 128);
    #pragma unroll
    for (int j = 0; j < 32; j++) {
        float4 h = __ldg(hp + j);
        hv2[2 * j]     = pack2(h.x, h.y);
        hv2[2 * j + 1] = pack2(h.z, h.w);
    }

    float y0 = sb2[0], y1 = sb2[1];
    #pragma unroll 2
    for (int k = 0; k < 128; k++) {
        u64 t0 = 0, t1 = 0, t2 = 0, t3 = 0;
        uint32_t ra = swa + k * (W1T_STRIDE * 4);
        #pragma unroll
        for (int j = 0; j < 32; j++) {
            u64 w0, w1v;
            lds_v2u64(w0, w1v, ra + (j << 4));
            fma2((j & 1) ? t1 : t0, hv2[2 * j],     w0);
            fma2((j & 1) ? t3 : t2, hv2[2 * j + 1], w1v);
        }
        float2 a = unpack2(t0), bq = unpack2(t1), c = unpack2(t2), d = unpack2(t3);
        float t = ((a.x + a.y) + (bq.x + bq.y)) + ((c.x + c.y) + (d.x + d.y)) + sb1[k];
        float s = silu(t);
        y0 += s * sW2[2 * k];
        y1 += s * sW2[2 * k + 1];
    }
    out[2 * v]     = y0;
    out[2 * v + 1] = y1;
}

// ---------------- launcher ----------------
extern "C" void kernel_launch(void* const* d_in, const int* in_sizes, int n_in,
                              void* d_out, int out_size)
{
    const float* x_lit  = (const float*)d_in[0];
    const float* x_cls  = (const float*)d_in[1];
    const int*   e_lit  = (const int*)  d_in[2];
    const int*   e_cls  = (const int*)  d_in[3];
    const float* enc_w1 = (const float*)d_in[4];
    const float* enc_b1 = (const float*)d_in[5];
    const float* enc_w2 = (const float*)d_in[6];
    const float* enc_b2 = (const float*)d_in[7];
    const float* Wc     = (const float*)d_in[8];
    const float* bc     = (const float*)d_in[9];
    const float* Wl     = (const float*)d_in[10];
    const float* bl     = (const float*)d_in[11];
    const float* out_w1 = (const float*)d_in[12];
    const float* out_b1 = (const float*)d_in[13];
    const float* out_w2 = (const float*)d_in[14];
    const float* out_b2 = (const float*)d_in[15];
    float* y = (float*)d_out;

    float *p_hlA, *p_hlB, *p_hc, *p_m, *p_inv;
    int *p_cnt, *p_rs, *p_cur, *p_adj;
    cudaGetSymbolAddress((void**)&p_hlA, g_hlA);
    cudaGetSymbolAddress((void**)&p_hlB, g_hlB);
    cudaGetSymbolAddress((void**)&p_hc,  g_hc);
    cudaGetSymbolAddress((void**)&p_m,   g_m);
    cudaGetSymbolAddress((void**)&p_cnt, g_cnt);
    cudaGetSymbolAddress((void**)&p_inv, g_inv);
    cudaGetSymbolAddress((void**)&p_rs,  g_rs);
    cudaGetSymbolAddress((void**)&p_cur, g_cur);
    cudaGetSymbolAddress((void**)&p_adj, g_adj);

    const int smem_cls = (64 * AST * 2 + 64 * WST * 2 + 64) * 4;   // 71,936 B
    const int smem_lit = (64 * AST * 2 + 96 * WST * 2 + 64) * 4;   // 90,368 B
    cudaFuncSetAttribute(cls_update, cudaFuncAttributeMaxDynamicSharedMemorySize, smem_cls);
    cudaFuncSetAttribute(lit_update, cudaFuncAttributeMaxDynamicSharedMemorySize, smem_lit);
    cudaFuncSetAttribute(readout_kernel, cudaFuncAttributeMaxDynamicSharedMemorySize,
                         (128 * W1T_STRIDE + 128 + 256 + 8) * 4);

    // 1) encoder + edge counting (cnt/tiles/ctr reset by previous call's fill / static init)
    encoder_kernel<<<(NT + 127) / 128, 128>>>(
        x_lit, x_cls, enc_w1, enc_b1, enc_w2, enc_b2,
        e_lit, e_cls, p_cnt, p_hlA, p_hc);

    // 2) single-pass scan -> rs, cur, inv
    int nb = (NT + SCAN_B - 1) / SCAN_B;
    scan_onepass<<<nb, SCAN_B>>>(p_cnt, p_rs, p_cur, p_inv, NT);

    // 3) adjacency fill + reset cnt/scan state
    fill_kernel<<<(NE + 255) / 256, 256>>>(e_lit, e_cls, p_cur, p_adj, p_cnt);

    // 4+) message-passing layers
    float* cur = p_hlA;
    float* nxt = p_hlB;
    for (int l = 0; l < NLAY; l++) {
        agg_kernel<<<((size_t)N_CLS * 32 + 255) / 256, 256>>>(
            cur, p_rs, p_adj, p_inv, p_m, N_CLS);
        cls_update<<<N_CLS / 64, 128, smem_cls>>>(
            p_hc, p_m, Wc + (size_t)l * 2 * CH * CH, bc + l * CH);
        agg_kernel<<<((size_t)N_LIT * 32 + 255) / 256, 256>>>(
            p_hc, p_rs + N_CLS, p_adj, p_inv + N_CLS, p_m, N_LIT);
        lit_update<<<N_LIT / 64, 128, smem_lit>>>(
            cur, nxt, p_m, Wl + (size_t)l * 3 * CH * CH, bl + l * CH);
        float* tmp = cur; cur = nxt; nxt = tmp;
    }

    // readout
    readout_kernel<<<(NVAR + 127) / 128, 128, (128 * W1T_STRIDE + 128 + 256 + 8) * 4>>>(
        cur, out_w1, out_b1, out_w2, out_b2, y);
}

// round 12
// speedup vs baseline: 1.1023x; 1.0313x over previous
#include <cuda_runtime.h>
#include <cuda_bf16.h>
#include <cstddef>
#include <cstdint>

#define N_LIT 200000
#define N_CLS 800000
#define NE    2400000
#define NT    (N_CLS + N_LIT)
#define CH    64
#define NVAR  (N_LIT/2)
#define NLAY  4
#define SCAN_B 1024

typedef unsigned long long u64;

// ---------------- device scratch (static, no allocation) ----------------
__device__ float g_hlA[(size_t)N_LIT * CH];
__device__ float g_hlB[(size_t)N_LIT * CH];
__device__ float g_hc [(size_t)N_CLS * CH];
__device__ float g_m  [(size_t)N_CLS * CH];
__device__ int   g_cnt[NT];          // zero-init; re-zeroed by fill_kernel each call
__device__ float g_inv[NT];
__device__ int   g_rs [NT + 1];
__device__ int   g_cur[NT];
__device__ int   g_adj[2 * NE];      // [0,NE): lits by clause; [NE,2NE): clauses by literal
__device__ u64   g_tiles[1024];      // decoupled-lookback state: (flag<<32)|value
__device__ unsigned int g_ctr;       // ticket counter

__device__ __forceinline__ float silu(float x) { return x / (1.0f + __expf(-x)); }

// ---- f32x2 packed helpers (encoder/readout scalar path) ----
__device__ __forceinline__ u64 pack2(float lo, float hi) {
    u64 r; asm("mov.b64 %0, {%1,%2};" : "=l"(r) : "f"(lo), "f"(hi)); return r;
}
__device__ __forceinline__ u64 pack_dup(float x) {
    u64 r; asm("mov.b64 %0, {%1,%1};" : "=l"(r) : "f"(x)); return r;
}
__device__ __forceinline__ void fma2(u64& acc, u64 a, u64 b) {
    asm("fma.rn.f32x2 %0, %1, %2, %0;" : "+l"(acc) : "l"(a), "l"(b));
}
__device__ __forceinline__ float2 unpack2(u64 v) {
    float2 f; asm("mov.b64 {%0,%1}, %2;" : "=f"(f.x), "=f"(f.y) : "l"(v)); return f;
}
__device__ __forceinline__ void lds_v2u64(u64& a, u64& b, uint32_t addr) {
    asm("ld.shared.v2.b64 {%0,%1}, [%2];" : "=l"(a), "=l"(b) : "r"(addr));
}

// ---- cache-policy memory helpers ----
// 64-bit access policy: fractional evict_last (pin) — built once per thread.
__device__ __forceinline__ u64 make_policy_evict_last() {
    u64 pol;
    asm("createpolicy.fractional.L2::evict_last.b64 %0, 1.0;" : "=l"(pol));
    return pol;
}
__device__ __forceinline__ float2 ldg_hint_f2(const float2* p, u64 pol) {
    float2 v;
    asm("ld.global.nc.L2::cache_hint.v2.f32 {%0,%1}, [%2], %3;"
        : "=f"(v.x), "=f"(v.y) : "l"(p), "l"(pol));
    return v;
}
__device__ __forceinline__ float2 ldg_f2(const float2* p) {
    float2 v;
    asm("ld.global.nc.v2.f32 {%0,%1}, [%2];" : "=f"(v.x), "=f"(v.y) : "l"(p));
    return v;
}
__device__ __forceinline__ void stg_cs_f2(float2* p, float2 v) {
    asm volatile("st.global.cs.v2.f32 [%0], {%1,%2};" :: "l"(p), "f"(v.x), "f"(v.y) : "memory");
}
__device__ __forceinline__ float2 ldg_cs_f2(const float2* p) {
    float2 v;
    asm("ld.global.cs.v2.f32 {%0,%1}, [%2];" : "=f"(v.x), "=f"(v.y) : "l"(p));
    return v;
}

// ---- bf16 split-pack: x = hi + lo (each bf16), packed as bf16x2 pairs along k ----
__device__ __forceinline__ void split2(float x0, float x1, uint32_t& hi, uint32_t& lo) {
    __nv_bfloat16 h0 = __float2bfloat16_rn(x0);
    __nv_bfloat16 h1 = __float2bfloat16_rn(x1);
    float r0 = x0 - __bfloat162float(h0);
    float r1 = x1 - __bfloat162float(h1);
    __nv_bfloat16 l0 = __float2bfloat16_rn(r0);
    __nv_bfloat16 l1 = __float2bfloat16_rn(r1);
    hi = ((uint32_t)__bfloat16_as_ushort(h1) << 16) | (uint32_t)__bfloat16_as_ushort(h0);
    lo = ((uint32_t)__bfloat16_as_ushort(l1) << 16) | (uint32_t)__bfloat16_as_ushort(l0);
}

// bf16 m16n8k16 MMA, fp32 accumulate
__device__ __forceinline__ void mma16816(float* c,
    uint32_t a0, uint32_t a1, uint32_t a2, uint32_t a3, uint32_t b0, uint32_t b1)
{
    asm("mma.sync.aligned.m16n8k16.row.col.f32.bf16.bf16.f32 "
        "{%0,%1,%2,%3}, {%4,%5,%6,%7}, {%8,%9}, {%0,%1,%2,%3};"
        : "+f"(c[0]), "+f"(c[1]), "+f"(c[2]), "+f"(c[3])
        : "r"(a0), "r"(a1), "r"(a2), "r"(a3), "r"(b0), "r"(b1));
}

// ---------------- 1) encoder + edge counting (fused) ----------------
__global__ void __launch_bounds__(128) encoder_kernel(
    const float* __restrict__ xl, const float* __restrict__ xc,
    const float* __restrict__ w1, const float* __restrict__ b1,
    const float* __restrict__ w2, const float* __restrict__ b2,
    const int* __restrict__ el, const int* __restrict__ ec,
    int* __restrict__ cnt,
    float* __restrict__ hl, float* __restrict__ hc)
{
    __shared__ __align__(16) float sW1[4 * CH];
    __shared__ __align__(16) float sb1[CH];
    __shared__ __align__(16) float sW2[CH * CH];
    __shared__ __align__(16) float sb2[CH];
    for (int t = threadIdx.x; t < 64; t += 128) ((float4*)sW1)[t] = ((const float4*)w1)[t];
    for (int t = threadIdx.x; t < CH * 16; t += 128) ((float4*)sW2)[t] = ((const float4*)w2)[t];
    if (threadIdx.x < CH) { sb1[threadIdx.x] = b1[threadIdx.x]; sb2[threadIdx.x] = b2[threadIdx.x]; }
    __syncthreads();
    uint32_t sw2a = (uint32_t)__cvta_generic_to_shared(sW2);

    int i = blockIdx.x * 128 + threadIdx.x;
    int stride = gridDim.x * 128;

    for (size_t e = i; e < NE; e += stride) {
        atomicAdd(cnt + __ldg(ec + e), 1);
        atomicAdd(cnt + N_CLS + __ldg(el + e), 1);
    }

    if (i >= NT) return;
    const float* x;
    float* out;
    if (i < N_LIT) { x = xl + (size_t)i * 4;           out = hl + (size_t)i * CH; }
    else           { x = xc + (size_t)(i - N_LIT) * 4; out = hc + (size_t)(i - N_LIT) * CH; }
    float4 xv = __ldg((const float4*)x);

    u64 acc2[32];
    #pragma unroll
    for (int j = 0; j < 16; j++) {
        float4 bv = ((const float4*)sb2)[j];
        acc2[2 * j]     = pack2(bv.x, bv.y);
        acc2[2 * j + 1] = pack2(bv.z, bv.w);
    }

    #pragma unroll 8
    for (int k = 0; k < CH; k++) {
        float t = sb1[k] + xv.x * sW1[k] + xv.y * sW1[CH + k] + xv.z * sW1[2 * CH + k] + xv.w * sW1[3 * CH + k];
        u64 s2 = pack_dup(silu(t));
        uint32_t ra = sw2a + (k << 8);
        #pragma unroll
        for (int j = 0; j < 16; j++) {
            u64 w0, w1v;
            lds_v2u64(w0, w1v, ra + (j << 4));
            fma2(acc2[2 * j],     s2, w0);
            fma2(acc2[2 * j + 1], s2, w1v);
        }
    }
    #pragma unroll
    for (int j = 0; j < 16; j++) {
        float2 a = unpack2(acc2[2 * j]);
        float2 b = unpack2(acc2[2 * j + 1]);
        ((float4*)out)[j] = make_float4(a.x, a.y, b.x, b.y);
    }
}

// ---------------- 2) single-pass scan (decoupled lookback, ticket-ordered) ----------------
__global__ void __launch_bounds__(SCAN_B) scan_onepass(
    const int* __restrict__ cnt, int* __restrict__ rs, int* __restrict__ cur,
    float* __restrict__ inv, int n)
{
    __shared__ int s[SCAN_B];
    __shared__ int sbid;
    __shared__ int sbase;
    if (threadIdx.x == 0) sbid = (int)atomicAdd(&g_ctr, 1u);
    __syncthreads();
    int bid = sbid;
    int i = bid * SCAN_B + threadIdx.x;
    int v = (i < n) ? cnt[i] : 0;
    s[threadIdx.x] = v;
    __syncthreads();
    for (int off = 1; off < SCAN_B; off <<= 1) {
        int t = (threadIdx.x >= off) ? s[threadIdx.x - off] : 0;
        __syncthreads();
        s[threadIdx.x] += t;
        __syncthreads();
    }
    if (threadIdx.x == 0) {
        int total = s[SCAN_B - 1];
        if (bid == 0) {
            atomicExch(&g_tiles[0], (2ull << 32) | (unsigned)total);
            sbase = 0;
        } else {
            atomicExch(&g_tiles[bid], (1ull << 32) | (unsigned)total);
            int base = 0;
            int t = bid - 1;
            while (t >= 0) {
                u64 st;
                do { st = atomicAdd(&g_tiles[t], 0ull); } while ((st >> 32) == 0ull);
                base += (int)(unsigned)st;
                if ((st >> 32) == 2ull) break;
                t--;
            }
            atomicExch(&g_tiles[bid], (2ull << 32) | (unsigned)(base + total));
            sbase = base;
        }
    }
    __syncthreads();
    int base = sbase;
    if (i < n) {
        int r = base + s[threadIdx.x] - v;
        rs[i] = r;
        cur[i] = r;
        inv[i] = (v > 0) ? (1.0f / (float)v) : 1.0f;
    }
    if (bid == 0 && threadIdx.x == 0) rs[n] = 2 * NE;
}

// ---------------- 3) adjacency fill (+ reset cnt / scan state for next call) ----------------
__global__ void fill_kernel(const int* __restrict__ el, const int* __restrict__ ec,
                            int* __restrict__ cur, int* __restrict__ adj,
                            int* __restrict__ cnt) {
    int e = blockIdx.x * 256 + threadIdx.x;
    if (e < NT) cnt[e] = 0;
    if (e < 1024) g_tiles[e] = 0ull;
    if (e == 0) g_ctr = 0u;
    if (e < NE) {
        int l = __ldg(el + e), c = __ldg(ec + e);
        adj[atomicAdd(cur + c, 1)]         = l;
        adj[atomicAdd(cur + N_CLS + l, 1)] = c;
    }
}

// ---------------- aggregation: warp-per-node gather, MLP=4, cache-policy hints ----------------
// EVICT_LAST=true when the gather source fits L2 (cls direction: hl = 51 MB).
template <bool EVICT_LAST>
__global__ void __launch_bounds__(256) agg_kernel(
    const float* __restrict__ src, const int* __restrict__ rs,
    const int* __restrict__ adj, const float* __restrict__ inv,
    float* __restrict__ m, int n)
{
    int w = (blockIdx.x * 256 + threadIdx.x) >> 5;
    if (w >= n) return;
    int lane = threadIdx.x & 31;
    u64 pol = EVICT_LAST ? make_policy_evict_last() : 0ull;
    int start = __ldg(rs + w), end = __ldg(rs + w + 1);
    const float2* base = (const float2*)src;
    float ax = 0.f, ay = 0.f;
    int p = start;
    for (; p + 4 <= end; p += 4) {
        int j0 = __ldg(adj + p),     j1 = __ldg(adj + p + 1);
        int j2 = __ldg(adj + p + 2), j3 = __ldg(adj + p + 3);
        const float2* p0 = base + (size_t)j0 * 32 + lane;
        const float2* p1 = base + (size_t)j1 * 32 + lane;
        const float2* p2 = base + (size_t)j2 * 32 + lane;
        const float2* p3 = base + (size_t)j3 * 32 + lane;
        float2 v0 = EVICT_LAST ? ldg_hint_f2(p0, pol) : ldg_f2(p0);
        float2 v1 = EVICT_LAST ? ldg_hint_f2(p1, pol) : ldg_f2(p1);
        float2 v2 = EVICT_LAST ? ldg_hint_f2(p2, pol) : ldg_f2(p2);
        float2 v3 = EVICT_LAST ? ldg_hint_f2(p3, pol) : ldg_f2(p3);
        ax += (v0.x + v1.x) + (v2.x + v3.x);
        ay += (v0.y + v1.y) + (v2.y + v3.y);
    }
    for (; p < end; p++) {
        int j = __ldg(adj + p);
        const float2* pp = base + (size_t)j * 32 + lane;
        float2 v = EVICT_LAST ? ldg_hint_f2(pp, pol) : ldg_f2(pp);
        ax += v.x; ay += v.y;
    }
    float iv = __ldg(inv + w);
    stg_cs_f2((float2*)m + (size_t)w * 32 + lane, make_float2(ax * iv, ay * iv));
}

// ================= HMMA update kernels =================
#define AST 68
#define WST 72

// ---- cls: hc = silu([hc, m] @ Wc + bc), K=128, in place ----
__global__ void __launch_bounds__(128) cls_update(
    float* __restrict__ hc, const float* __restrict__ m,
    const float* __restrict__ W, const float* __restrict__ b)
{
    extern __shared__ uint32_t smu[];
    uint32_t* sAh = smu;                   // 64*68
    uint32_t* sAl = sAh + 64 * AST;
    uint32_t* sWh = sAl + 64 * AST;        // 64*72
    uint32_t* sWl = sWh + 64 * WST;
    float*    sb  = (float*)(sWl + 64 * WST);

    int tid = threadIdx.x;
    size_t gbase = (size_t)blockIdx.x * 64;

    for (int idx = tid; idx < 64 * 64; idx += 128) {
        int p = idx >> 6, c = idx & 63;
        float w0 = __ldg(W + (size_t)(2 * p) * 64 + c);
        float w1 = __ldg(W + (size_t)(2 * p + 1) * 64 + c);
        uint32_t hi, lo; split2(w0, w1, hi, lo);
        sWh[p * WST + c] = hi; sWl[p * WST + c] = lo;
    }
    for (int idx = tid; idx < 64 * 32; idx += 128) {
        int nd = idx >> 5, pj = idx & 31;
        float2 v = __ldg((const float2*)(hc + (gbase + nd) * CH) + pj);
        uint32_t hi, lo; split2(v.x, v.y, hi, lo);
        sAh[nd * AST + pj] = hi; sAl[nd * AST + pj] = lo;
        float2 vm = ldg_cs_f2((const float2*)(m + (gbase + nd) * CH) + pj);
        split2(vm.x, vm.y, hi, lo);
        sAh[nd * AST + 32 + pj] = hi; sAl[nd * AST + 32 + pj] = lo;
    }
    if (tid < 64) sb[tid] = b[tid];
    __syncthreads();

    int lane = tid & 31, warp = tid >> 5;
    int g = lane >> 2, t4 = lane & 3;
    int r0 = warp * 16 + g;

    float c[8][4];
    #pragma unroll
    for (int nt = 0; nt < 8; nt++) { c[nt][0] = c[nt][1] = c[nt][2] = c[nt][3] = 0.f; }

    #pragma unroll
    for (int s = 0; s < 8; s++) {
        int pb = s * 8 + t4;
        uint32_t ah0 = sAh[r0 * AST + pb],       ah1 = sAh[(r0 + 8) * AST + pb];
        uint32_t ah2 = sAh[r0 * AST + pb + 4],   ah3 = sAh[(r0 + 8) * AST + pb + 4];
        uint32_t al0 = sAl[r0 * AST + pb],       al1 = sAl[(r0 + 8) * AST + pb];
        uint32_t al2 = sAl[r0 * AST + pb + 4],   al3 = sAl[(r0 + 8) * AST + pb + 4];
        #pragma unroll
        for (int nt = 0; nt < 8; nt++) {
            int wc = nt * 8 + g;
            uint32_t bh0 = sWh[pb * WST + wc], bh1 = sWh[(pb + 4) * WST + wc];
            uint32_t bl0 = sWl[pb * WST + wc], bl1 = sWl[(pb + 4) * WST + wc];
            mma16816(c[nt], ah0, ah1, ah2, ah3, bh0, bh1);
            mma16816(c[nt], ah0, ah1, ah2, ah3, bl0, bl1);
            mma16816(c[nt], al0, al1, al2, al3, bh0, bh1);
        }
    }

    size_t row0 = gbase + r0, row1 = row0 + 8;
    #pragma unroll
    for (int nt = 0; nt < 8; nt++) {
        int col = nt * 8 + 2 * t4;
        float b0 = sb[col], b1 = sb[col + 1];
        *(float2*)(hc + row0 * CH + col) = make_float2(silu(c[nt][0] + b0), silu(c[nt][1] + b1));
        *(float2*)(hc + row1 * CH + col) = make_float2(silu(c[nt][2] + b0), silu(c[nt][3] + b1));
    }
}

// ---- lit: hdst = silu([hsrc, m, hsrc_flip] @ Wl + bl), K=192 ----
__global__ void __launch_bounds__(128) lit_update(
    const float* __restrict__ hsrc, float* __restrict__ hdst,
    const float* __restrict__ m,
    const float* __restrict__ W, const float* __restrict__ b)
{
    extern __shared__ uint32_t smu[];
    uint32_t* sAh = smu;                   // 64*68 (self pairs 0..31, m pairs 32..63)
    uint32_t* sAl = sAh + 64 * AST;
    uint32_t* sWh = sAl + 64 * AST;        // 96*72
    uint32_t* sWl = sWh + 96 * WST;
    float*    sb  = (float*)(sWl + 96 * WST);

    int tid = threadIdx.x;
    size_t gbase = (size_t)blockIdx.x * 64;

    for (int idx = tid; idx < 96 * 64; idx += 128) {
        int p = idx >> 6, c = idx & 63;
        float w0 = __ldg(W + (size_t)(2 * p) * 64 + c);
        float w1 = __ldg(W + (size_t)(2 * p + 1) * 64 + c);
        uint32_t hi, lo; split2(w0, w1, hi, lo);
        sWh[p * WST + c] = hi; sWl[p * WST + c] = lo;
    }
    for (int idx = tid; idx < 64 * 32; idx += 128) {
        int nd = idx >> 5, pj = idx & 31;
        float2 v = __ldg((const float2*)(hsrc + (gbase + nd) * CH) + pj);
        uint32_t hi, lo; split2(v.x, v.y, hi, lo);
        sAh[nd * AST + pj] = hi; sAl[nd * AST + pj] = lo;
        float2 vm = ldg_cs_f2((const float2*)(m + (gbase + nd) * CH) + pj);
        split2(vm.x, vm.y, hi, lo);
        sAh[nd * AST + 32 + pj] = hi; sAl[nd * AST + 32 + pj] = lo;
    }
    if (tid < 64) sb[tid] = b[tid];
    __syncthreads();

    int lane = tid & 31, warp = tid >> 5;
    int g = lane >> 2, t4 = lane & 3;
    int r0 = warp * 16 + g;

    float c[8][4];
    #pragma unroll
    for (int nt = 0; nt < 8; nt++) { c[nt][0] = c[nt][1] = c[nt][2] = c[nt][3] = 0.f; }

    #pragma unroll
    for (int s = 0; s < 8; s++) {
        int pb = s * 8 + t4;
        uint32_t ah0 = sAh[r0 * AST + pb],       ah1 = sAh[(r0 + 8) * AST + pb];
        uint32_t ah2 = sAh[r0 * AST + pb + 4],   ah3 = sAh[(r0 + 8) * AST + pb + 4];
        uint32_t al0 = sAl[r0 * AST + pb],       al1 = sAl[(r0 + 8) * AST + pb];
        uint32_t al2 = sAl[r0 * AST + pb + 4],   al3 = sAl[(r0 + 8) * AST + pb + 4];
        #pragma unroll
        for (int nt = 0; nt < 8; nt++) {
            int wc = nt * 8 + g;
            uint32_t bh0 = sWh[pb * WST + wc], bh1 = sWh[(pb + 4) * WST + wc];
            uint32_t bl0 = sWl[pb * WST + wc], bl1 = sWl[(pb + 4) * WST + wc];
            mma16816(c[nt], ah0, ah1, ah2, ah3, bh0, bh1);
            mma16816(c[nt], ah0, ah1, ah2, ah3, bl0, bl1);
            mma16816(c[nt], al0, al1, al2, al3, bh0, bh1);
        }
    }
    int f0 = r0 ^ 1, f1 = (r0 + 8) ^ 1;
    #pragma unroll
    for (int s = 0; s < 4; s++) {
        int pa = s * 8 + t4;
        int pw = 64 + s * 8 + t4;
        uint32_t ah0 = sAh[f0 * AST + pa],       ah1 = sAh[f1 * AST + pa];
        uint32_t ah2 = sAh[f0 * AST + pa + 4],   ah3 = sAh[f1 * AST + pa + 4];
        uint32_t al0 = sAl[f0 * AST + pa],       al1 = sAl[f1 * AST + pa];
        uint32_t al2 = sAl[f0 * AST + pa + 4],   al3 = sAl[f1 * AST + pa + 4];
        #pragma unroll
        for (int nt = 0; nt < 8; nt++) {
            int wc = nt * 8 + g;
            uint32_t bh0 = sWh[pw * WST + wc], bh1 = sWh[(pw + 4) * WST + wc];
            uint32_t bl0 = sWl[pw * WST + wc], bl1 = sWl[(pw + 4) * WST + wc];
            mma16816(c[nt], ah0, ah1, ah2, ah3, bh0, bh1);
            mma16816(c[nt], ah0, ah1, ah2, ah3, bl0, bl1);
            mma16816(c[nt], al0, al1, al2, al3, bh0, bh1);
        }
    }

    size_t row0 = gbase + r0, row1 = row0 + 8;
    #pragma unroll
    for (int nt = 0; nt < 8; nt++) {
        int col = nt * 8 + 2 * t4;
        float b0 = sb[col], b1 = sb[col + 1];
        *(float2*)(hdst + row0 * CH + col) = make_float2(silu(c[nt][0] + b0), silu(c[nt][1] + b1));
        *(float2*)(hdst + row1 * CH + col) = make_float2(silu(c[nt][2] + b0), silu(c[nt][3] + b1));
    }
}

// ---------------- readout ----------------
#define W1T_STRIDE 132   // floats; 528B, 16B-aligned
__global__ void __launch_bounds__(128) readout_kernel(
    const float* __restrict__ hl,
    const float* __restrict__ w1, const float* __restrict__ b1,
    const float* __restrict__ w2, const float* __restrict__ b2,
    float* __restrict__ out)
{
    extern __shared__ __align__(16) float smem[];
    float* sW1T = smem;                       // [128][132] transposed, padded
    float* sb1  = smem + 128 * W1T_STRIDE;
    float* sW2  = sb1 + 128;
    float* sb2  = sW2 + 256;
    for (int t = threadIdx.x; t < 128 * 128; t += 128) {
        int i = t >> 7, k = t & 127;
        sW1T[k * W1T_STRIDE + i] = w1[t];     // w1[i][k]
    }
    sb1[threadIdx.x] = b1[threadIdx.x];
    for (int t = threadIdx.x; t < 256; t += 128) sW2[t] = w2[t];
    if (threadIdx.x < 2) sb2[threadIdx.x] = b2[threadIdx.x];
    __syncthreads();
    uint32_t swa = (uint32_t)__cvta_generic_to_shared(sW1T);

    int v = blockIdx.x * 128 + threadIdx.x;
    if (v >= NVAR) return;

    u64 hv2[64];
    const float4* hp = (const float4*)(hl + (size_t)v * 128);
    #pragma unroll
    for (int j = 0; j < 32; j++) {
        float4 h = __ldg(hp + j);
        hv2[2 * j]     = pack2(h.x, h.y);
        hv2[2 * j + 1] = pack2(h.z, h.w);
    }

    float y0 = sb2[0], y1 = sb2[1];
    #pragma unroll 2
    for (int k = 0; k < 128; k++) {
        u64 t0 = 0, t1 = 0, t2 = 0, t3 = 0;
        uint32_t ra = swa + k * (W1T_STRIDE * 4);
        #pragma unroll
        for (int j = 0; j < 32; j++) {
            u64 w0, w1v;
            lds_v2u64(w0, w1v, ra + (j << 4));
            fma2((j & 1) ? t1 : t0, hv2[2 * j],     w0);
            fma2((j & 1) ? t3 : t2, hv2[2 * j + 1], w1v);
        }
        float2 a = unpack2(t0), bq = unpack2(t1), c = unpack2(t2), d = unpack2(t3);
        float t = ((a.x + a.y) + (bq.x + bq.y)) + ((c.x + c.y) + (d.x + d.y)) + sb1[k];
        float s = silu(t);
        y0 += s * sW2[2 * k];
        y1 += s * sW2[2 * k + 1];
    }
    out[2 * v]     = y0;
    out[2 * v + 1] = y1;
}

// ---------------- launcher ----------------
extern "C" void kernel_launch(void* const* d_in, const int* in_sizes, int n_in,
                              void* d_out, int out_size)
{
    const float* x_lit  = (const float*)d_in[0];
    const float* x_cls  = (const float*)d_in[1];
    const int*   e_lit  = (const int*)  d_in[2];
    const int*   e_cls  = (const int*)  d_in[3];
    const float* enc_w1 = (const float*)d_in[4];
    const float* enc_b1 = (const float*)d_in[5];
    const float* enc_w2 = (const float*)d_in[6];
    const float* enc_b2 = (const float*)d_in[7];
    const float* Wc     = (const float*)d_in[8];
    const float* bc     = (const float*)d_in[9];
    const float* Wl     = (const float*)d_in[10];
    const float* bl     = (const float*)d_in[11];
    const float* out_w1 = (const float*)d_in[12];
    const float* out_b1 = (const float*)d_in[13];
    const float* out_w2 = (const float*)d_in[14];
    const float* out_b2 = (const float*)d_in[15];
    float* y = (float*)d_out;

    float *p_hlA, *p_hlB, *p_hc, *p_m, *p_inv;
    int *p_cnt, *p_rs, *p_cur, *p_adj;
    cudaGetSymbolAddress((void**)&p_hlA, g_hlA);
    cudaGetSymbolAddress((void**)&p_hlB, g_hlB);
    cudaGetSymbolAddress((void**)&p_hc,  g_hc);
    cudaGetSymbolAddress((void**)&p_m,   g_m);
    cudaGetSymbolAddress((void**)&p_cnt, g_cnt);
    cudaGetSymbolAddress((void**)&p_inv, g_inv);
    cudaGetSymbolAddress((void**)&p_rs,  g_rs);
    cudaGetSymbolAddress((void**)&p_cur, g_cur);
    cudaGetSymbolAddress((void**)&p_adj, g_adj);

    const int smem_cls = (64 * AST * 2 + 64 * WST * 2 + 64) * 4;
    const int smem_lit = (64 * AST * 2 + 96 * WST * 2 + 64) * 4;
    cudaFuncSetAttribute(cls_update, cudaFuncAttributeMaxDynamicSharedMemorySize, smem_cls);
    cudaFuncSetAttribute(lit_update, cudaFuncAttributeMaxDynamicSharedMemorySize, smem_lit);
    cudaFuncSetAttribute(readout_kernel, cudaFuncAttributeMaxDynamicSharedMemorySize,
                         (128 * W1T_STRIDE + 128 + 256 + 8) * 4);

    // 1) encoder + edge counting (cnt/tiles/ctr reset by previous call's fill / static init)
    encoder_kernel<<<(NT + 127) / 128, 128>>>(
        x_lit, x_cls, enc_w1, enc_b1, enc_w2, enc_b2,
        e_lit, e_cls, p_cnt, p_hlA, p_hc);

    // 2) single-pass scan -> rs, cur, inv
    int nb = (NT + SCAN_B - 1) / SCAN_B;
    scan_onepass<<<nb, SCAN_B>>>(p_cnt, p_rs, p_cur, p_inv, NT);

    // 3) adjacency fill + reset cnt/scan state
    fill_kernel<<<(NE + 255) / 256, 256>>>(e_lit, e_cls, p_cur, p_adj, p_cnt);

    // 4+) message-passing layers
    float* cur = p_hlA;
    float* nxt = p_hlB;
    for (int l = 0; l < NLAY; l++) {
        // lit -> cls: source hl (51 MB) fits L2 -> pin with evict_last policy
        agg_kernel<true><<<((size_t)N_CLS * 32 + 255) / 256, 256>>>(
            cur, p_rs, p_adj, p_inv, p_m, N_CLS);
        cls_update<<<N_CLS / 64, 128, smem_cls>>>(
            p_hc, p_m, Wc + (size_t)l * 2 * CH * CH, bc + l * CH);
        // cls -> lit: source hc (205 MB) exceeds L2 -> default policy
        agg_kernel<false><<<((size_t)N_LIT * 32 + 255) / 256, 256>>>(
            p_hc, p_rs + N_CLS, p_adj, p_inv + N_CLS, p_m, N_LIT);
        lit_update<<<N_LIT / 64, 128, smem_lit>>>(
            cur, nxt, p_m, Wl + (size_t)l * 3 * CH * CH, bl + l * CH);
        float* tmp = cur; cur = nxt; nxt = tmp;
    }

    // readout
    readout_kernel<<<(NVAR + 127) / 128, 128, (128 * W1T_STRIDE + 128 + 256 + 8) * 4>>>(
        cur, out_w1, out_b1, out_w2, out_b2, y);
}

// round 13
// speedup vs baseline: 1.1056x; 1.0031x over previous
#include <cuda_runtime.h>
#include <cuda_bf16.h>
#include <cstddef>
#include <cstdint>

#define N_LIT 200000
#define N_CLS 800000
#define NE    2400000
#define NT    (N_CLS + N_LIT)
#define CH    64
#define NVAR  (N_LIT/2)
#define NLAY  4
#define SCAN_B 1024

typedef unsigned long long u64;

// ---------------- device scratch (static, no allocation) ----------------
__device__ float g_hlA[(size_t)N_LIT * CH];
__device__ float g_hlB[(size_t)N_LIT * CH];
__device__ float g_hc [(size_t)N_CLS * CH];
__device__ float g_m  [(size_t)N_CLS * CH];
__device__ int   g_cnt[NT];          // zero-init; re-zeroed by fill_kernel each call
__device__ float g_inv[NT];
__device__ int   g_rs [NT + 1];
__device__ int   g_cur[NT];
__device__ int   g_adj[2 * NE];      // [0,NE): lits by clause; [NE,2NE): clauses by literal
__device__ u64   g_tiles[1024];      // decoupled-lookback state: (flag<<32)|value
__device__ unsigned int g_ctr;       // ticket counter

__device__ __forceinline__ float silu(float x) { return x / (1.0f + __expf(-x)); }

// ---- f32x2 packed helpers (encoder/readout scalar path) ----
__device__ __forceinline__ u64 pack2(float lo, float hi) {
    u64 r; asm("mov.b64 %0, {%1,%2};" : "=l"(r) : "f"(lo), "f"(hi)); return r;
}
__device__ __forceinline__ u64 pack_dup(float x) {
    u64 r; asm("mov.b64 %0, {%1,%1};" : "=l"(r) : "f"(x)); return r;
}
__device__ __forceinline__ void fma2(u64& acc, u64 a, u64 b) {
    asm("fma.rn.f32x2 %0, %1, %2, %0;" : "+l"(acc) : "l"(a), "l"(b));
}
__device__ __forceinline__ float2 unpack2(u64 v) {
    float2 f; asm("mov.b64 {%0,%1}, %2;" : "=f"(f.x), "=f"(f.y) : "l"(v)); return f;
}
__device__ __forceinline__ void lds_v2u64(u64& a, u64& b, uint32_t addr) {
    asm("ld.shared.v2.b64 {%0,%1}, [%2];" : "=l"(a), "=l"(b) : "r"(addr));
}

// ---- cache-policy memory helpers ----
__device__ __forceinline__ u64 make_policy_evict_last() {
    u64 pol;
    asm("createpolicy.fractional.L2::evict_last.b64 %0, 1.0;" : "=l"(pol));
    return pol;
}
__device__ __forceinline__ float2 ldg_hint_f2(const float2* p, u64 pol) {
    float2 v;
    asm("ld.global.nc.L2::cache_hint.v2.f32 {%0,%1}, [%2], %3;"
        : "=f"(v.x), "=f"(v.y) : "l"(p), "l"(pol));
    return v;
}
__device__ __forceinline__ float2 ldg_f2(const float2* p) {
    float2 v;
    asm("ld.global.nc.v2.f32 {%0,%1}, [%2];" : "=f"(v.x), "=f"(v.y) : "l"(p));
    return v;
}
__device__ __forceinline__ void stg_cs_f2(float2* p, float2 v) {
    asm volatile("st.global.cs.v2.f32 [%0], {%1,%2};" :: "l"(p), "f"(v.x), "f"(v.y) : "memory");
}
__device__ __forceinline__ float2 ldg_cs_f2(const float2* p) {
    float2 v;
    asm("ld.global.cs.v2.f32 {%0,%1}, [%2];" : "=f"(v.x), "=f"(v.y) : "l"(p));
    return v;
}

// ---- bf16 split-pack: x = hi + lo (each bf16), packed as bf16x2 pairs along k ----
__device__ __forceinline__ void split2(float x0, float x1, uint32_t& hi, uint32_t& lo) {
    __nv_bfloat16 h0 = __float2bfloat16_rn(x0);
    __nv_bfloat16 h1 = __float2bfloat16_rn(x1);
    float r0 = x0 - __bfloat162float(h0);
    float r1 = x1 - __bfloat162float(h1);
    __nv_bfloat16 l0 = __float2bfloat16_rn(r0);
    __nv_bfloat16 l1 = __float2bfloat16_rn(r1);
    hi = ((uint32_t)__bfloat16_as_ushort(h1) << 16) | (uint32_t)__bfloat16_as_ushort(h0);
    lo = ((uint32_t)__bfloat16_as_ushort(l1) << 16) | (uint32_t)__bfloat16_as_ushort(l0);
}

// bf16 m16n8k16 MMA, fp32 accumulate
__device__ __forceinline__ void mma16816(float* c,
    uint32_t a0, uint32_t a1, uint32_t a2, uint32_t a3, uint32_t b0, uint32_t b1)
{
    asm("mma.sync.aligned.m16n8k16.row.col.f32.bf16.bf16.f32 "
        "{%0,%1,%2,%3}, {%4,%5,%6,%7}, {%8,%9}, {%0,%1,%2,%3};"
        : "+f"(c[0]), "+f"(c[1]), "+f"(c[2]), "+f"(c[3])
        : "r"(a0), "r"(a1), "r"(a2), "r"(a3), "r"(b0), "r"(b1));
}

// ---------------- 1) encoder + edge counting (fused) ----------------
__global__ void __launch_bounds__(128) encoder_kernel(
    const float* __restrict__ xl, const float* __restrict__ xc,
    const float* __restrict__ w1, const float* __restrict__ b1,
    const float* __restrict__ w2, const float* __restrict__ b2,
    const int* __restrict__ el, const int* __restrict__ ec,
    int* __restrict__ cnt,
    float* __restrict__ hl, float* __restrict__ hc)
{
    __shared__ __align__(16) float sW1[4 * CH];
    __shared__ __align__(16) float sb1[CH];
    __shared__ __align__(16) float sW2[CH * CH];
    __shared__ __align__(16) float sb2[CH];
    for (int t = threadIdx.x; t < 64; t += 128) ((float4*)sW1)[t] = ((const float4*)w1)[t];
    for (int t = threadIdx.x; t < CH * 16; t += 128) ((float4*)sW2)[t] = ((const float4*)w2)[t];
    if (threadIdx.x < CH) { sb1[threadIdx.x] = b1[threadIdx.x]; sb2[threadIdx.x] = b2[threadIdx.x]; }
    __syncthreads();
    uint32_t sw2a = (uint32_t)__cvta_generic_to_shared(sW2);

    int i = blockIdx.x * 128 + threadIdx.x;
    int stride = gridDim.x * 128;

    for (size_t e = i; e < NE; e += stride) {
        atomicAdd(cnt + __ldg(ec + e), 1);
        atomicAdd(cnt + N_CLS + __ldg(el + e), 1);
    }

    if (i >= NT) return;
    const float* x;
    float* out;
    if (i < N_LIT) { x = xl + (size_t)i * 4;           out = hl + (size_t)i * CH; }
    else           { x = xc + (size_t)(i - N_LIT) * 4; out = hc + (size_t)(i - N_LIT) * CH; }
    float4 xv = __ldg((const float4*)x);

    u64 acc2[32];
    #pragma unroll
    for (int j = 0; j < 16; j++) {
        float4 bv = ((const float4*)sb2)[j];
        acc2[2 * j]     = pack2(bv.x, bv.y);
        acc2[2 * j + 1] = pack2(bv.z, bv.w);
    }

    #pragma unroll 8
    for (int k = 0; k < CH; k++) {
        float t = sb1[k] + xv.x * sW1[k] + xv.y * sW1[CH + k] + xv.z * sW1[2 * CH + k] + xv.w * sW1[3 * CH + k];
        u64 s2 = pack_dup(silu(t));
        uint32_t ra = sw2a + (k << 8);
        #pragma unroll
        for (int j = 0; j < 16; j++) {
            u64 w0, w1v;
            lds_v2u64(w0, w1v, ra + (j << 4));
            fma2(acc2[2 * j],     s2, w0);
            fma2(acc2[2 * j + 1], s2, w1v);
        }
    }
    #pragma unroll
    for (int j = 0; j < 16; j++) {
        float2 a = unpack2(acc2[2 * j]);
        float2 b = unpack2(acc2[2 * j + 1]);
        ((float4*)out)[j] = make_float4(a.x, a.y, b.x, b.y);
    }
}

// ---------------- 2) single-pass scan (decoupled lookback, ticket-ordered) ----------------
__global__ void __launch_bounds__(SCAN_B) scan_onepass(
    const int* __restrict__ cnt, int* __restrict__ rs, int* __restrict__ cur,
    float* __restrict__ inv, int n)
{
    __shared__ int s[SCAN_B];
    __shared__ int sbid;
    __shared__ int sbase;
    if (threadIdx.x == 0) sbid = (int)atomicAdd(&g_ctr, 1u);
    __syncthreads();
    int bid = sbid;
    int i = bid * SCAN_B + threadIdx.x;
    int v = (i < n) ? cnt[i] : 0;
    s[threadIdx.x] = v;
    __syncthreads();
    for (int off = 1; off < SCAN_B; off <<= 1) {
        int t = (threadIdx.x >= off) ? s[threadIdx.x - off] : 0;
        __syncthreads();
        s[threadIdx.x] += t;
        __syncthreads();
    }
    if (threadIdx.x == 0) {
        int total = s[SCAN_B - 1];
        if (bid == 0) {
            atomicExch(&g_tiles[0], (2ull << 32) | (unsigned)total);
            sbase = 0;
        } else {
            atomicExch(&g_tiles[bid], (1ull << 32) | (unsigned)total);
            int base = 0;
            int t = bid - 1;
            while (t >= 0) {
                u64 st;
                do { st = atomicAdd(&g_tiles[t], 0ull); } while ((st >> 32) == 0ull);
                base += (int)(unsigned)st;
                if ((st >> 32) == 2ull) break;
                t--;
            }
            atomicExch(&g_tiles[bid], (2ull << 32) | (unsigned)(base + total));
            sbase = base;
        }
    }
    __syncthreads();
    int base = sbase;
    if (i < n) {
        int r = base + s[threadIdx.x] - v;
        rs[i] = r;
        cur[i] = r;
        inv[i] = (v > 0) ? (1.0f / (float)v) : 1.0f;
    }
    if (bid == 0 && threadIdx.x == 0) rs[n] = 2 * NE;
}

// ---------------- 3) adjacency fill (+ reset cnt / scan state for next call) ----------------
__global__ void fill_kernel(const int* __restrict__ el, const int* __restrict__ ec,
                            int* __restrict__ cur, int* __restrict__ adj,
                            int* __restrict__ cnt) {
    int e = blockIdx.x * 256 + threadIdx.x;
    if (e < NT) cnt[e] = 0;
    if (e < 1024) g_tiles[e] = 0ull;
    if (e == 0) g_ctr = 0u;
    if (e < NE) {
        int l = __ldg(el + e), c = __ldg(ec + e);
        adj[atomicAdd(cur + c, 1)]         = l;
        adj[atomicAdd(cur + N_CLS + l, 1)] = c;
    }
}

// ---------------- aggregation: warp-per-node gather, masked 4-wide chunks ----------------
// Every chunk issues 4 independent adj loads + 4 independent gathers (clamped to the
// chunk's first slot when out of range; contribution zeroed by mask). This removes the
// serial adj->gather tail chain that dominated at mean degree 3.
template <bool EVICT_LAST>
__global__ void __launch_bounds__(256) agg_kernel(
    const float* __restrict__ src, const int* __restrict__ rs,
    const int* __restrict__ adj, const float* __restrict__ inv,
    float* __restrict__ m, int n)
{
    int w = (blockIdx.x * 256 + threadIdx.x) >> 5;
    if (w >= n) return;
    int lane = threadIdx.x & 31;
    u64 pol = EVICT_LAST ? make_policy_evict_last() : 0ull;
    int start = __ldg(rs + w), end = __ldg(rs + w + 1);
    const float2* base = (const float2*)src;
    float ax = 0.f, ay = 0.f;
    for (int p0 = start; p0 < end; p0 += 4) {
        int r = end - p0;                                  // >= 1
        int j0 = __ldg(adj + p0);
        int j1 = (r > 1) ? __ldg(adj + p0 + 1) : j0;
        int j2 = (r > 2) ? __ldg(adj + p0 + 2) : j0;
        int j3 = (r > 3) ? __ldg(adj + p0 + 3) : j0;
        const float2* q0 = base + (size_t)j0 * 32 + lane;
        const float2* q1 = base + (size_t)j1 * 32 + lane;
        const float2* q2 = base + (size_t)j2 * 32 + lane;
        const float2* q3 = base + (size_t)j3 * 32 + lane;
        float2 v0 = EVICT_LAST ? ldg_hint_f2(q0, pol) : ldg_f2(q0);
        float2 v1 = EVICT_LAST ? ldg_hint_f2(q1, pol) : ldg_f2(q1);
        float2 v2 = EVICT_LAST ? ldg_hint_f2(q2, pol) : ldg_f2(q2);
        float2 v3 = EVICT_LAST ? ldg_hint_f2(q3, pol) : ldg_f2(q3);
        float m1 = (r > 1) ? 1.f : 0.f;
        float m2 = (r > 2) ? 1.f : 0.f;
        float m3 = (r > 3) ? 1.f : 0.f;
        ax += v0.x + m1 * v1.x + m2 * v2.x + m3 * v3.x;
        ay += v0.y + m1 * v1.y + m2 * v2.y + m3 * v3.y;
    }
    float iv = __ldg(inv + w);
    stg_cs_f2((float2*)m + (size_t)w * 32 + lane, make_float2(ax * iv, ay * iv));
}

// ================= HMMA update kernels =================
#define AST 68
#define WST 72

// ---- cls: hc = silu([hc, m] @ Wc + bc), K=128, in place ----
__global__ void __launch_bounds__(128) cls_update(
    float* __restrict__ hc, const float* __restrict__ m,
    const float* __restrict__ W, const float* __restrict__ b)
{
    extern __shared__ uint32_t smu[];
    uint32_t* sAh = smu;                   // 64*68
    uint32_t* sAl = sAh + 64 * AST;
    uint32_t* sWh = sAl + 64 * AST;        // 64*72
    uint32_t* sWl = sWh + 64 * WST;
    float*    sb  = (float*)(sWl + 64 * WST);

    int tid = threadIdx.x;
    size_t gbase = (size_t)blockIdx.x * 64;

    for (int idx = tid; idx < 64 * 64; idx += 128) {
        int p = idx >> 6, c = idx & 63;
        float w0 = __ldg(W + (size_t)(2 * p) * 64 + c);
        float w1 = __ldg(W + (size_t)(2 * p + 1) * 64 + c);
        uint32_t hi, lo; split2(w0, w1, hi, lo);
        sWh[p * WST + c] = hi; sWl[p * WST + c] = lo;
    }
    for (int idx = tid; idx < 64 * 32; idx += 128) {
        int nd = idx >> 5, pj = idx & 31;
        float2 v = __ldg((const float2*)(hc + (gbase + nd) * CH) + pj);
        uint32_t hi, lo; split2(v.x, v.y, hi, lo);
        sAh[nd * AST + pj] = hi; sAl[nd * AST + pj] = lo;
        float2 vm = ldg_cs_f2((const float2*)(m + (gbase + nd) * CH) + pj);
        split2(vm.x, vm.y, hi, lo);
        sAh[nd * AST + 32 + pj] = hi; sAl[nd * AST + 32 + pj] = lo;
    }
    if (tid < 64) sb[tid] = b[tid];
    __syncthreads();

    int lane = tid & 31, warp = tid >> 5;
    int g = lane >> 2, t4 = lane & 3;
    int r0 = warp * 16 + g;

    float c[8][4];
    #pragma unroll
    for (int nt = 0; nt < 8; nt++) { c[nt][0] = c[nt][1] = c[nt][2] = c[nt][3] = 0.f; }

    #pragma unroll
    for (int s = 0; s < 8; s++) {
        int pb = s * 8 + t4;
        uint32_t ah0 = sAh[r0 * AST + pb],       ah1 = sAh[(r0 + 8) * AST + pb];
        uint32_t ah2 = sAh[r0 * AST + pb + 4],   ah3 = sAh[(r0 + 8) * AST + pb + 4];
        uint32_t al0 = sAl[r0 * AST + pb],       al1 = sAl[(r0 + 8) * AST + pb];
        uint32_t al2 = sAl[r0 * AST + pb + 4],   al3 = sAl[(r0 + 8) * AST + pb + 4];
        #pragma unroll
        for (int nt = 0; nt < 8; nt++) {
            int wc = nt * 8 + g;
            uint32_t bh0 = sWh[pb * WST + wc], bh1 = sWh[(pb + 4) * WST + wc];
            uint32_t bl0 = sWl[pb * WST + wc], bl1 = sWl[(pb + 4) * WST + wc];
            mma16816(c[nt], ah0, ah1, ah2, ah3, bh0, bh1);
            mma16816(c[nt], ah0, ah1, ah2, ah3, bl0, bl1);
            mma16816(c[nt], al0, al1, al2, al3, bh0, bh1);
        }
    }

    size_t row0 = gbase + r0, row1 = row0 + 8;
    #pragma unroll
    for (int nt = 0; nt < 8; nt++) {
        int col = nt * 8 + 2 * t4;
        float b0 = sb[col], b1 = sb[col + 1];
        *(float2*)(hc + row0 * CH + col) = make_float2(silu(c[nt][0] + b0), silu(c[nt][1] + b1));
        *(float2*)(hc + row1 * CH + col) = make_float2(silu(c[nt][2] + b0), silu(c[nt][3] + b1));
    }
}

// ---- lit: hdst = silu([hsrc, m, hsrc_flip] @ Wl + bl), K=192 ----
__global__ void __launch_bounds__(128) lit_update(
    const float* __restrict__ hsrc, float* __restrict__ hdst,
    const float* __restrict__ m,
    const float* __restrict__ W, const float* __restrict__ b)
{
    extern __shared__ uint32_t smu[];
    uint32_t* sAh = smu;                   // 64*68 (self pairs 0..31, m pairs 32..63)
    uint32_t* sAl = sAh + 64 * AST;
    uint32_t* sWh = sAl + 64 * AST;        // 96*72
    uint32_t* sWl = sWh + 96 * WST;
    float*    sb  = (float*)(sWl + 96 * WST);

    int tid = threadIdx.x;
    size_t gbase = (size_t)blockIdx.x * 64;

    for (int idx = tid; idx < 96 * 64; idx += 128) {
        int p = idx >> 6, c = idx & 63;
        float w0 = __ldg(W + (size_t)(2 * p) * 64 + c);
        float w1 = __ldg(W + (size_t)(2 * p + 1) * 64 + c);
        uint32_t hi, lo; split2(w0, w1, hi, lo);
        sWh[p * WST + c] = hi; sWl[p * WST + c] = lo;
    }
    for (int idx = tid; idx < 64 * 32; idx += 128) {
        int nd = idx >> 5, pj = idx & 31;
        float2 v = __ldg((const float2*)(hsrc + (gbase + nd) * CH) + pj);
        uint32_t hi, lo; split2(v.x, v.y, hi, lo);
        sAh[nd * AST + pj] = hi; sAl[nd * AST + pj] = lo;
        float2 vm = ldg_cs_f2((const float2*)(m + (gbase + nd) * CH) + pj);
        split2(vm.x, vm.y, hi, lo);
        sAh[nd * AST + 32 + pj] = hi; sAl[nd * AST + 32 + pj] = lo;
    }
    if (tid < 64) sb[tid] = b[tid];
    __syncthreads();

    int lane = tid & 31, warp = tid >> 5;
    int g = lane >> 2, t4 = lane & 3;
    int r0 = warp * 16 + g;

    float c[8][4];
    #pragma unroll
    for (int nt = 0; nt < 8; nt++) { c[nt][0] = c[nt][1] = c[nt][2] = c[nt][3] = 0.f; }

    #pragma unroll
    for (int s = 0; s < 8; s++) {
        int pb = s * 8 + t4;
        uint32_t ah0 = sAh[r0 * AST + pb],       ah1 = sAh[(r0 + 8) * AST + pb];
        uint32_t ah2 = sAh[r0 * AST + pb + 4],   ah3 = sAh[(r0 + 8) * AST + pb + 4];
        uint32_t al0 = sAl[r0 * AST + pb],       al1 = sAl[(r0 + 8) * AST + pb];
        uint32_t al2 = sAl[r0 * AST + pb + 4],   al3 = sAl[(r0 + 8) * AST + pb + 4];
        #pragma unroll
        for (int nt = 0; nt < 8; nt++) {
            int wc = nt * 8 + g;
            uint32_t bh0 = sWh[pb * WST + wc], bh1 = sWh[(pb + 4) * WST + wc];
            uint32_t bl0 = sWl[pb * WST + wc], bl1 = sWl[(pb + 4) * WST + wc];
            mma16816(c[nt], ah0, ah1, ah2, ah3, bh0, bh1);
            mma16816(c[nt], ah0, ah1, ah2, ah3, bl0, bl1);
            mma16816(c[nt], al0, al1, al2, al3, bh0, bh1);
        }
    }
    int f0 = r0 ^ 1, f1 = (r0 + 8) ^ 1;
    #pragma unroll
    for (int s = 0; s < 4; s++) {
        int pa = s * 8 + t4;
        int pw = 64 + s * 8 + t4;
        uint32_t ah0 = sAh[f0 * AST + pa],       ah1 = sAh[f1 * AST + pa];
        uint32_t ah2 = sAh[f0 * AST + pa + 4],   ah3 = sAh[f1 * AST + pa + 4];
        uint32_t al0 = sAl[f0 * AST + pa],       al1 = sAl[f1 * AST + pa];
        uint32_t al2 = sAl[f0 * AST + pa + 4],   al3 = sAl[f1 * AST + pa + 4];
        #pragma unroll
        for (int nt = 0; nt < 8; nt++) {
            int wc = nt * 8 + g;
            uint32_t bh0 = sWh[pw * WST + wc], bh1 = sWh[(pw + 4) * WST + wc];
            uint32_t bl0 = sWl[pw * WST + wc], bl1 = sWl[(pw + 4) * WST + wc];
            mma16816(c[nt], ah0, ah1, ah2, ah3, bh0, bh1);
            mma16816(c[nt], ah0, ah1, ah2, ah3, bl0, bl1);
            mma16816(c[nt], al0, al1, al2, al3, bh0, bh1);
        }
    }

    size_t row0 = gbase + r0, row1 = row0 + 8;
    #pragma unroll
    for (int nt = 0; nt < 8; nt++) {
        int col = nt * 8 + 2 * t4;
        float b0 = sb[col], b1 = sb[col + 1];
        *(float2*)(hdst + row0 * CH + col) = make_float2(silu(c[nt][0] + b0), silu(c[nt][1] + b1));
        *(float2*)(hdst + row1 * CH + col) = make_float2(silu(c[nt][2] + b0), silu(c[nt][3] + b1));
    }
}

// ---------------- readout ----------------
#define W1T_STRIDE 132   // floats; 528B, 16B-aligned
__global__ void __launch_bounds__(128) readout_kernel(
    const float* __restrict__ hl,
    const float* __restrict__ w1, const float* __restrict__ b1,
    const float* __restrict__ w2, const float* __restrict__ b2,
    float* __restrict__ out)
{
    extern __shared__ __align__(16) float smem[];
    float* sW1T = smem;                       // [128][132] transposed, padded
    float* sb1  = smem + 128 * W1T_STRIDE;
    float* sW2  = sb1 + 128;
    float* sb2  = sW2 + 256;
    for (int t = threadIdx.x; t < 128 * 128; t += 128) {
        int i = t >> 7, k = t & 127;
        sW1T[k * W1T_STRIDE + i] = w1[t];     // w1[i][k]
    }
    sb1[threadIdx.x] = b1[threadIdx.x];
    for (int t = threadIdx.x; t < 256; t += 128) sW2[t] = w2[t];
    if (threadIdx.x < 2) sb2[threadIdx.x] = b2[threadIdx.x];
    __syncthreads();
    uint32_t swa = (uint32_t)__cvta_generic_to_shared(sW1T);

    int v = blockIdx.x * 128 + threadIdx.x;
    if (v >= NVAR) return;

    u64 hv2[64];
    const float4* hp = (const float4*)(hl + (size_t)v * 128);
    #pragma unroll
    for (int j = 0; j < 32; j++) {
        float4 h = __ldg(hp + j);
        hv2[2 * j]     = pack2(h.x, h.y);
        hv2[2 * j + 1] = pack2(h.z, h.w);
    }

    float y0 = sb2[0], y1 = sb2[1];
    #pragma unroll 2
    for (int k = 0; k < 128; k++) {
        u64 t0 = 0, t1 = 0, t2 = 0, t3 = 0;
        uint32_t ra = swa + k * (W1T_STRIDE * 4);
        #pragma unroll
        for (int j = 0; j < 32; j++) {
            u64 w0, w1v;
            lds_v2u64(w0, w1v, ra + (j << 4));
            fma2((j & 1) ? t1 : t0, hv2[2 * j],     w0);
            fma2((j & 1) ? t3 : t2, hv2[2 * j + 1], w1v);
        }
        float2 a = unpack2(t0), bq = unpack2(t1), c = unpack2(t2), d = unpack2(t3);
        float t = ((a.x + a.y) + (bq.x + bq.y)) + ((c.x + c.y) + (d.x + d.y)) + sb1[k];
        float s = silu(t);
        y0 += s * sW2[2 * k];
        y1 += s * sW2[2 * k + 1];
    }
    out[2 * v]     = y0;
    out[2 * v + 1] = y1;
}

// ---------------- launcher ----------------
extern "C" void kernel_launch(void* const* d_in, const int* in_sizes, int n_in,
                              void* d_out, int out_size)
{
    const float* x_lit  = (const float*)d_in[0];
    const float* x_cls  = (const float*)d_in[1];
    const int*   e_lit  = (const int*)  d_in[2];
    const int*   e_cls  = (const int*)  d_in[3];
    const float* enc_w1 = (const float*)d_in[4];
    const float* enc_b1 = (const float*)d_in[5];
    const float* enc_w2 = (const float*)d_in[6];
    const float* enc_b2 = (const float*)d_in[7];
    const float* Wc     = (const float*)d_in[8];
    const float* bc     = (const float*)d_in[9];
    const float* Wl     = (const float*)d_in[10];
    const float* bl     = (const float*)d_in[11];
    const float* out_w1 = (const float*)d_in[12];
    const float* out_b1 = (const float*)d_in[13];
    const float* out_w2 = (const float*)d_in[14];
    const float* out_b2 = (const float*)d_in[15];
    float* y = (float*)d_out;

    float *p_hlA, *p_hlB, *p_hc, *p_m, *p_inv;
    int *p_cnt, *p_rs, *p_cur, *p_adj;
    cudaGetSymbolAddress((void**)&p_hlA, g_hlA);
    cudaGetSymbolAddress((void**)&p_hlB, g_hlB);
    cudaGetSymbolAddress((void**)&p_hc,  g_hc);
    cudaGetSymbolAddress((void**)&p_m,   g_m);
    cudaGetSymbolAddress((void**)&p_cnt, g_cnt);
    cudaGetSymbolAddress((void**)&p_inv, g_inv);
    cudaGetSymbolAddress((void**)&p_rs,  g_rs);
    cudaGetSymbolAddress((void**)&p_cur, g_cur);
    cudaGetSymbolAddress((void**)&p_adj, g_adj);

    const int smem_cls = (64 * AST * 2 + 64 * WST * 2 + 64) * 4;
    const int smem_lit = (64 * AST * 2 + 96 * WST * 2 + 64) * 4;
    cudaFuncSetAttribute(cls_update, cudaFuncAttributeMaxDynamicSharedMemorySize, smem_cls);
    cudaFuncSetAttribute(lit_update, cudaFuncAttributeMaxDynamicSharedMemorySize, smem_lit);
    cudaFuncSetAttribute(readout_kernel, cudaFuncAttributeMaxDynamicSharedMemorySize,
                         (128 * W1T_STRIDE + 128 + 256 + 8) * 4);

    // 1) encoder + edge counting (cnt/tiles/ctr reset by previous call's fill / static init)
    encoder_kernel<<<(NT + 127) / 128, 128>>>(
        x_lit, x_cls, enc_w1, enc_b1, enc_w2, enc_b2,
        e_lit, e_cls, p_cnt, p_hlA, p_hc);

    // 2) single-pass scan -> rs, cur, inv
    int nb = (NT + SCAN_B - 1) / SCAN_B;
    scan_onepass<<<nb, SCAN_B>>>(p_cnt, p_rs, p_cur, p_inv, NT);

    // 3) adjacency fill + reset cnt/scan state
    fill_kernel<<<(NE + 255) / 256, 256>>>(e_lit, e_cls, p_cur, p_adj, p_cnt);

    // 4+) message-passing layers
    float* cur = p_hlA;
    float* nxt = p_hlB;
    for (int l = 0; l < NLAY; l++) {
        // lit -> cls: source hl (51 MB) fits L2 -> pin with evict_last policy
        agg_kernel<true><<<((size_t)N_CLS * 32 + 255) / 256, 256>>>(
            cur, p_rs, p_adj, p_inv, p_m, N_CLS);
        cls_update<<<N_CLS / 64, 128, smem_cls>>>(
            p_hc, p_m, Wc + (size_t)l * 2 * CH * CH, bc + l * CH);
        // cls -> lit: source hc (205 MB) exceeds L2 -> default policy
        agg_kernel<false><<<((size_t)N_LIT * 32 + 255) / 256, 256>>>(
            p_hc, p_rs + N_CLS, p_adj, p_inv + N_CLS, p_m, N_LIT);
        lit_update<<<N_LIT / 64, 128, smem_lit>>>(
            cur, nxt, p_m, Wl + (size_t)l * 3 * CH * CH, bl + l * CH);
        float* tmp = cur; cur = nxt; nxt = tmp;
    }

    // readout
    readout_kernel<<<(NVAR + 127) / 128, 128, (128 * W1T_STRIDE + 128 + 256 + 8) * 4>>>(
        cur, out_w1, out_b1, out_w2, out_b2, y);
}

// round 14
// speedup vs baseline: 1.1109x; 1.0048x over previous
#include <cuda_runtime.h>
#include <cuda_bf16.h>
#include <cuda_fp16.h>
#include <cstddef>
#include <cstdint>

#define N_LIT 200000
#define N_CLS 800000
#define NE    2400000
#define NT    (N_CLS + N_LIT)
#define CH    64
#define NVAR  (N_LIT/2)
#define NLAY  4
#define SCAN_B 1024

typedef unsigned long long u64;

// ---------------- device scratch (static, no allocation) ----------------
__device__ float g_hlA[(size_t)N_LIT * CH];
__device__ float g_hlB[(size_t)N_LIT * CH];
__device__ float g_hc [(size_t)N_CLS * CH];
__device__ float g_m  [(size_t)N_CLS * CH];
__device__ __half g_hl16[(size_t)N_LIT * CH];   // fp16 shadow of current hl (gather source)
__device__ __half g_hc16[(size_t)N_CLS * CH];   // fp16 shadow of hc (gather source)
__device__ int   g_cnt[NT];          // zero-init; re-zeroed by fill_kernel each call
__device__ float g_inv[NT];
__device__ int   g_rs [NT + 1];
__device__ int   g_cur[NT];
__device__ int   g_adj[2 * NE];      // [0,NE): lits by clause; [NE,2NE): clauses by literal
__device__ u64   g_tiles[1024];      // decoupled-lookback state: (flag<<32)|value
__device__ unsigned int g_ctr;       // ticket counter

__device__ __forceinline__ float silu(float x) { return x / (1.0f + __expf(-x)); }

// ---- f32x2 packed helpers (encoder/readout scalar path) ----
__device__ __forceinline__ u64 pack2(float lo, float hi) {
    u64 r; asm("mov.b64 %0, {%1,%2};" : "=l"(r) : "f"(lo), "f"(hi)); return r;
}
__device__ __forceinline__ u64 pack_dup(float x) {
    u64 r; asm("mov.b64 %0, {%1,%1};" : "=l"(r) : "f"(x)); return r;
}
__device__ __forceinline__ void fma2(u64& acc, u64 a, u64 b) {
    asm("fma.rn.f32x2 %0, %1, %2, %0;" : "+l"(acc) : "l"(a), "l"(b));
}
__device__ __forceinline__ float2 unpack2(u64 v) {
    float2 f; asm("mov.b64 {%0,%1}, %2;" : "=f"(f.x), "=f"(f.y) : "l"(v)); return f;
}
__device__ __forceinline__ void lds_v2u64(u64& a, u64& b, uint32_t addr) {
    asm("ld.shared.v2.b64 {%0,%1}, [%2];" : "=l"(a), "=l"(b) : "r"(addr));
}

// ---- cache-policy memory helpers ----
__device__ __forceinline__ u64 make_policy_evict_last() {
    u64 pol;
    asm("createpolicy.fractional.L2::evict_last.b64 %0, 1.0;" : "=l"(pol));
    return pol;
}
__device__ __forceinline__ uint32_t ldg_hint_u32(const uint32_t* p, u64 pol) {
    uint32_t v;
    asm("ld.global.nc.L2::cache_hint.b32 %0, [%1], %2;" : "=r"(v) : "l"(p), "l"(pol));
    return v;
}
__device__ __forceinline__ void stg_cs_f2(float2* p, float2 v) {
    asm volatile("st.global.cs.v2.f32 [%0], {%1,%2};" :: "l"(p), "f"(v.x), "f"(v.y) : "memory");
}
__device__ __forceinline__ float2 ldg_cs_f2(const float2* p) {
    float2 v;
    asm("ld.global.cs.v2.f32 {%0,%1}, [%2];" : "=f"(v.x), "=f"(v.y) : "l"(p));
    return v;
}
__device__ __forceinline__ float2 h2f2(uint32_t u) {
    __half2 h;
    *reinterpret_cast<uint32_t*>(&h) = u;
    return __half22float2(h);
}

// ---- bf16 split-pack: x = hi + lo (each bf16), packed as bf16x2 pairs along k ----
__device__ __forceinline__ void split2(float x0, float x1, uint32_t& hi, uint32_t& lo) {
    __nv_bfloat16 h0 = __float2bfloat16_rn(x0);
    __nv_bfloat16 h1 = __float2bfloat16_rn(x1);
    float r0 = x0 - __bfloat162float(h0);
    float r1 = x1 - __bfloat162float(h1);
    __nv_bfloat16 l0 = __float2bfloat16_rn(r0);
    __nv_bfloat16 l1 = __float2bfloat16_rn(r1);
    hi = ((uint32_t)__bfloat16_as_ushort(h1) << 16) | (uint32_t)__bfloat16_as_ushort(h0);
    lo = ((uint32_t)__bfloat16_as_ushort(l1) << 16) | (uint32_t)__bfloat16_as_ushort(l0);
}

// bf16 m16n8k16 MMA, fp32 accumulate
__device__ __forceinline__ void mma16816(float* c,
    uint32_t a0, uint32_t a1, uint32_t a2, uint32_t a3, uint32_t b0, uint32_t b1)
{
    asm("mma.sync.aligned.m16n8k16.row.col.f32.bf16.bf16.f32 "
        "{%0,%1,%2,%3}, {%4,%5,%6,%7}, {%8,%9}, {%0,%1,%2,%3};"
        : "+f"(c[0]), "+f"(c[1]), "+f"(c[2]), "+f"(c[3])
        : "r"(a0), "r"(a1), "r"(a2), "r"(a3), "r"(b0), "r"(b1));
}

// ---------------- 1) encoder + edge counting (fused) ----------------
__global__ void __launch_bounds__(128) encoder_kernel(
    const float* __restrict__ xl, const float* __restrict__ xc,
    const float* __restrict__ w1, const float* __restrict__ b1,
    const float* __restrict__ w2, const float* __restrict__ b2,
    const int* __restrict__ el, const int* __restrict__ ec,
    int* __restrict__ cnt,
    float* __restrict__ hl, float* __restrict__ hc,
    __half* __restrict__ hl16, __half* __restrict__ hc16)
{
    __shared__ __align__(16) float sW1[4 * CH];
    __shared__ __align__(16) float sb1[CH];
    __shared__ __align__(16) float sW2[CH * CH];
    __shared__ __align__(16) float sb2[CH];
    for (int t = threadIdx.x; t < 64; t += 128) ((float4*)sW1)[t] = ((const float4*)w1)[t];
    for (int t = threadIdx.x; t < CH * 16; t += 128) ((float4*)sW2)[t] = ((const float4*)w2)[t];
    if (threadIdx.x < CH) { sb1[threadIdx.x] = b1[threadIdx.x]; sb2[threadIdx.x] = b2[threadIdx.x]; }
    __syncthreads();
    uint32_t sw2a = (uint32_t)__cvta_generic_to_shared(sW2);

    int i = blockIdx.x * 128 + threadIdx.x;
    int stride = gridDim.x * 128;

    for (size_t e = i; e < NE; e += stride) {
        atomicAdd(cnt + __ldg(ec + e), 1);
        atomicAdd(cnt + N_CLS + __ldg(el + e), 1);
    }

    if (i >= NT) return;
    const float* x;
    float* out;
    __half* out16;
    if (i < N_LIT) { x = xl + (size_t)i * 4;           out = hl + (size_t)i * CH; out16 = hl16 + (size_t)i * CH; }
    else           { x = xc + (size_t)(i - N_LIT) * 4; out = hc + (size_t)(i - N_LIT) * CH; out16 = hc16 + (size_t)(i - N_LIT) * CH; }
    float4 xv = __ldg((const float4*)x);

    u64 acc2[32];
    #pragma unroll
    for (int j = 0; j < 16; j++) {
        float4 bv = ((const float4*)sb2)[j];
        acc2[2 * j]     = pack2(bv.x, bv.y);
        acc2[2 * j + 1] = pack2(bv.z, bv.w);
    }

    #pragma unroll 8
    for (int k = 0; k < CH; k++) {
        float t = sb1[k] + xv.x * sW1[k] + xv.y * sW1[CH + k] + xv.z * sW1[2 * CH + k] + xv.w * sW1[3 * CH + k];
        u64 s2 = pack_dup(silu(t));
        uint32_t ra = sw2a + (k << 8);
        #pragma unroll
        for (int j = 0; j < 16; j++) {
            u64 w0, w1v;
            lds_v2u64(w0, w1v, ra + (j << 4));
            fma2(acc2[2 * j],     s2, w0);
            fma2(acc2[2 * j + 1], s2, w1v);
        }
    }
    __half2* o16 = (__half2*)out16;
    #pragma unroll
    for (int j = 0; j < 16; j++) {
        float2 a = unpack2(acc2[2 * j]);
        float2 b = unpack2(acc2[2 * j + 1]);
        ((float4*)out)[j] = make_float4(a.x, a.y, b.x, b.y);
        o16[2 * j]     = __floats2half2_rn(a.x, a.y);
        o16[2 * j + 1] = __floats2half2_rn(b.x, b.y);
    }
}

// ---------------- 2) single-pass scan (decoupled lookback, ticket-ordered) ----------------
__global__ void __launch_bounds__(SCAN_B) scan_onepass(
    const int* __restrict__ cnt, int* __restrict__ rs, int* __restrict__ cur,
    float* __restrict__ inv, int n)
{
    __shared__ int s[SCAN_B];
    __shared__ int sbid;
    __shared__ int sbase;
    if (threadIdx.x == 0) sbid = (int)atomicAdd(&g_ctr, 1u);
    __syncthreads();
    int bid = sbid;
    int i = bid * SCAN_B + threadIdx.x;
    int v = (i < n) ? cnt[i] : 0;
    s[threadIdx.x] = v;
    __syncthreads();
    for (int off = 1; off < SCAN_B; off <<= 1) {
        int t = (threadIdx.x >= off) ? s[threadIdx.x - off] : 0;
        __syncthreads();
        s[threadIdx.x] += t;
        __syncthreads();
    }
    if (threadIdx.x == 0) {
        int total = s[SCAN_B - 1];
        if (bid == 0) {
            atomicExch(&g_tiles[0], (2ull << 32) | (unsigned)total);
            sbase = 0;
        } else {
            atomicExch(&g_tiles[bid], (1ull << 32) | (unsigned)total);
            int base = 0;
            int t = bid - 1;
            while (t >= 0) {
                u64 st;
                do { st = atomicAdd(&g_tiles[t], 0ull); } while ((st >> 32) == 0ull);
                base += (int)(unsigned)st;
                if ((st >> 32) == 2ull) break;
                t--;
            }
            atomicExch(&g_tiles[bid], (2ull << 32) | (unsigned)(base + total));
            sbase = base;
        }
    }
    __syncthreads();
    int base = sbase;
    if (i < n) {
        int r = base + s[threadIdx.x] - v;
        rs[i] = r;
        cur[i] = r;
        inv[i] = (v > 0) ? (1.0f / (float)v) : 1.0f;
    }
    if (bid == 0 && threadIdx.x == 0) rs[n] = 2 * NE;
}

// ---------------- 3) adjacency fill (+ reset cnt / scan state for next call) ----------------
__global__ void fill_kernel(const int* __restrict__ el, const int* __restrict__ ec,
                            int* __restrict__ cur, int* __restrict__ adj,
                            int* __restrict__ cnt) {
    int e = blockIdx.x * 256 + threadIdx.x;
    if (e < NT) cnt[e] = 0;
    if (e < 1024) g_tiles[e] = 0ull;
    if (e == 0) g_ctr = 0u;
    if (e < NE) {
        int l = __ldg(el + e), c = __ldg(ec + e);
        adj[atomicAdd(cur + c, 1)]         = l;
        adj[atomicAdd(cur + N_CLS + l, 1)] = c;
    }
}

// ---------------- aggregation: warp-per-node, fp16 source, masked 4-wide chunks ----------------
// src: fp16 rows of 64 ch = 128 B; lane covers channels 2*lane, 2*lane+1 (one b32 load).
__global__ void __launch_bounds__(256) agg_kernel(
    const __half* __restrict__ src, const int* __restrict__ rs,
    const int* __restrict__ adj, const float* __restrict__ inv,
    float* __restrict__ m, int n)
{
    int w = (blockIdx.x * 256 + threadIdx.x) >> 5;
    if (w >= n) return;
    int lane = threadIdx.x & 31;
    u64 pol = make_policy_evict_last();
    int start = __ldg(rs + w), end = __ldg(rs + w + 1);
    const uint32_t* base = (const uint32_t*)src;
    float ax = 0.f, ay = 0.f;
    for (int p0 = start; p0 < end; p0 += 4) {
        int r = end - p0;                                  // >= 1
        int j0 = __ldg(adj + p0);
        int j1 = (r > 1) ? __ldg(adj + p0 + 1) : j0;
        int j2 = (r > 2) ? __ldg(adj + p0 + 2) : j0;
        int j3 = (r > 3) ? __ldg(adj + p0 + 3) : j0;
        uint32_t u0 = ldg_hint_u32(base + (size_t)j0 * 32 + lane, pol);
        uint32_t u1 = ldg_hint_u32(base + (size_t)j1 * 32 + lane, pol);
        uint32_t u2 = ldg_hint_u32(base + (size_t)j2 * 32 + lane, pol);
        uint32_t u3 = ldg_hint_u32(base + (size_t)j3 * 32 + lane, pol);
        float2 v0 = h2f2(u0), v1 = h2f2(u1), v2 = h2f2(u2), v3 = h2f2(u3);
        float m1 = (r > 1) ? 1.f : 0.f;
        float m2 = (r > 2) ? 1.f : 0.f;
        float m3 = (r > 3) ? 1.f : 0.f;
        ax += v0.x + m1 * v1.x + m2 * v2.x + m3 * v3.x;
        ay += v0.y + m1 * v1.y + m2 * v2.y + m3 * v3.y;
    }
    float iv = __ldg(inv + w);
    stg_cs_f2((float2*)m + (size_t)w * 32 + lane, make_float2(ax * iv, ay * iv));
}

// ================= HMMA update kernels =================
#define AST 68
#define WST 72

// ---- cls: hc = silu([hc, m] @ Wc + bc), K=128, in place; also writes hc16 shadow ----
__global__ void __launch_bounds__(128) cls_update(
    float* __restrict__ hc, const float* __restrict__ m,
    const float* __restrict__ W, const float* __restrict__ b,
    __half* __restrict__ hc16)
{
    extern __shared__ uint32_t smu[];
    uint32_t* sAh = smu;                   // 64*68
    uint32_t* sAl = sAh + 64 * AST;
    uint32_t* sWh = sAl + 64 * AST;        // 64*72
    uint32_t* sWl = sWh + 64 * WST;
    float*    sb  = (float*)(sWl + 64 * WST);

    int tid = threadIdx.x;
    size_t gbase = (size_t)blockIdx.x * 64;

    for (int idx = tid; idx < 64 * 64; idx += 128) {
        int p = idx >> 6, c = idx & 63;
        float w0 = __ldg(W + (size_t)(2 * p) * 64 + c);
        float w1 = __ldg(W + (size_t)(2 * p + 1) * 64 + c);
        uint32_t hi, lo; split2(w0, w1, hi, lo);
        sWh[p * WST + c] = hi; sWl[p * WST + c] = lo;
    }
    for (int idx = tid; idx < 64 * 32; idx += 128) {
        int nd = idx >> 5, pj = idx & 31;
        float2 v = __ldg((const float2*)(hc + (gbase + nd) * CH) + pj);
        uint32_t hi, lo; split2(v.x, v.y, hi, lo);
        sAh[nd * AST + pj] = hi; sAl[nd * AST + pj] = lo;
        float2 vm = ldg_cs_f2((const float2*)(m + (gbase + nd) * CH) + pj);
        split2(vm.x, vm.y, hi, lo);
        sAh[nd * AST + 32 + pj] = hi; sAl[nd * AST + 32 + pj] = lo;
    }
    if (tid < 64) sb[tid] = b[tid];
    __syncthreads();

    int lane = tid & 31, warp = tid >> 5;
    int g = lane >> 2, t4 = lane & 3;
    int r0 = warp * 16 + g;

    float c[8][4];
    #pragma unroll
    for (int nt = 0; nt < 8; nt++) { c[nt][0] = c[nt][1] = c[nt][2] = c[nt][3] = 0.f; }

    #pragma unroll
    for (int s = 0; s < 8; s++) {
        int pb = s * 8 + t4;
        uint32_t ah0 = sAh[r0 * AST + pb],       ah1 = sAh[(r0 + 8) * AST + pb];
        uint32_t ah2 = sAh[r0 * AST + pb + 4],   ah3 = sAh[(r0 + 8) * AST + pb + 4];
        uint32_t al0 = sAl[r0 * AST + pb],       al1 = sAl[(r0 + 8) * AST + pb];
        uint32_t al2 = sAl[r0 * AST + pb + 4],   al3 = sAl[(r0 + 8) * AST + pb + 4];
        #pragma unroll
        for (int nt = 0; nt < 8; nt++) {
            int wc = nt * 8 + g;
            uint32_t bh0 = sWh[pb * WST + wc], bh1 = sWh[(pb + 4) * WST + wc];
            uint32_t bl0 = sWl[pb * WST + wc], bl1 = sWl[(pb + 4) * WST + wc];
            mma16816(c[nt], ah0, ah1, ah2, ah3, bh0, bh1);
            mma16816(c[nt], ah0, ah1, ah2, ah3, bl0, bl1);
            mma16816(c[nt], al0, al1, al2, al3, bh0, bh1);
        }
    }

    size_t row0 = gbase + r0, row1 = row0 + 8;
    __half2* h16r0 = (__half2*)(hc16 + row0 * CH);
    __half2* h16r1 = (__half2*)(hc16 + row1 * CH);
    #pragma unroll
    for (int nt = 0; nt < 8; nt++) {
        int col = nt * 8 + 2 * t4;
        float b0 = sb[col], b1 = sb[col + 1];
        float s00 = silu(c[nt][0] + b0), s01 = silu(c[nt][1] + b1);
        float s10 = silu(c[nt][2] + b0), s11 = silu(c[nt][3] + b1);
        *(float2*)(hc + row0 * CH + col) = make_float2(s00, s01);
        *(float2*)(hc + row1 * CH + col) = make_float2(s10, s11);
        h16r0[col >> 1] = __floats2half2_rn(s00, s01);
        h16r1[col >> 1] = __floats2half2_rn(s10, s11);
    }
}

// ---- lit: hdst = silu([hsrc, m, hsrc_flip] @ Wl + bl), K=192; also writes hl16 shadow ----
__global__ void __launch_bounds__(128) lit_update(
    const float* __restrict__ hsrc, float* __restrict__ hdst,
    const float* __restrict__ m,
    const float* __restrict__ W, const float* __restrict__ b,
    __half* __restrict__ hl16)
{
    extern __shared__ uint32_t smu[];
    uint32_t* sAh = smu;                   // 64*68 (self pairs 0..31, m pairs 32..63)
    uint32_t* sAl = sAh + 64 * AST;
    uint32_t* sWh = sAl + 64 * AST;        // 96*72
    uint32_t* sWl = sWh + 96 * WST;
    float*    sb  = (float*)(sWl + 96 * WST);

    int tid = threadIdx.x;
    size_t gbase = (size_t)blockIdx.x * 64;

    for (int idx = tid; idx < 96 * 64; idx += 128) {
        int p = idx >> 6, c = idx & 63;
        float w0 = __ldg(W + (size_t)(2 * p) * 64 + c);
        float w1 = __ldg(W + (size_t)(2 * p + 1) * 64 + c);
        uint32_t hi, lo; split2(w0, w1, hi, lo);
        sWh[p * WST + c] = hi; sWl[p * WST + c] = lo;
    }
    for (int idx = tid; idx < 64 * 32; idx += 128) {
        int nd = idx >> 5, pj = idx & 31;
        float2 v = __ldg((const float2*)(hsrc + (gbase + nd) * CH) + pj);
        uint32_t hi, lo; split2(v.x, v.y, hi, lo);
        sAh[nd * AST + pj] = hi; sAl[nd * AST + pj] = lo;
        float2 vm = ldg_cs_f2((const float2*)(m + (gbase + nd) * CH) + pj);
        split2(vm.x, vm.y, hi, lo);
        sAh[nd * AST + 32 + pj] = hi; sAl[nd * AST + 32 + pj] = lo;
    }
    if (tid < 64) sb[tid] = b[tid];
    __syncthreads();

    int lane = tid & 31, warp = tid >> 5;
    int g = lane >> 2, t4 = lane & 3;
    int r0 = warp * 16 + g;

    float c[8][4];
    #pragma unroll
    for (int nt = 0; nt < 8; nt++) { c[nt][0] = c[nt][1] = c[nt][2] = c[nt][3] = 0.f; }

    #pragma unroll
    for (int s = 0; s < 8; s++) {
        int pb = s * 8 + t4;
        uint32_t ah0 = sAh[r0 * AST + pb],       ah1 = sAh[(r0 + 8) * AST + pb];
        uint32_t ah2 = sAh[r0 * AST + pb + 4],   ah3 = sAh[(r0 + 8) * AST + pb + 4];
        uint32_t al0 = sAl[r0 * AST + pb],       al1 = sAl[(r0 + 8) * AST + pb];
        uint32_t al2 = sAl[r0 * AST + pb + 4],   al3 = sAl[(r0 + 8) * AST + pb + 4];
        #pragma unroll
        for (int nt = 0; nt < 8; nt++) {
            int wc = nt * 8 + g;
            uint32_t bh0 = sWh[pb * WST + wc], bh1 = sWh[(pb + 4) * WST + wc];
            uint32_t bl0 = sWl[pb * WST + wc], bl1 = sWl[(pb + 4) * WST + wc];
            mma16816(c[nt], ah0, ah1, ah2, ah3, bh0, bh1);
            mma16816(c[nt], ah0, ah1, ah2, ah3, bl0, bl1);
            mma16816(c[nt], al0, al1, al2, al3, bh0, bh1);
        }
    }
    int f0 = r0 ^ 1, f1 = (r0 + 8) ^ 1;
    #pragma unroll
    for (int s = 0; s < 4; s++) {
        int pa = s * 8 + t4;
        int pw = 64 + s * 8 + t4;
        uint32_t ah0 = sAh[f0 * AST + pa],       ah1 = sAh[f1 * AST + pa];
        uint32_t ah2 = sAh[f0 * AST + pa + 4],   ah3 = sAh[f1 * AST + pa + 4];
        uint32_t al0 = sAl[f0 * AST + pa],       al1 = sAl[f1 * AST + pa];
        uint32_t al2 = sAl[f0 * AST + pa + 4],   al3 = sAl[f1 * AST + pa + 4];
        #pragma unroll
        for (int nt = 0; nt < 8; nt++) {
            int wc = nt * 8 + g;
            uint32_t bh0 = sWh[pw * WST + wc], bh1 = sWh[(pw + 4) * WST + wc];
            uint32_t bl0 = sWl[pw * WST + wc], bl1 = sWl[(pw + 4) * WST + wc];
            mma16816(c[nt], ah0, ah1, ah2, ah3, bh0, bh1);
            mma16816(c[nt], ah0, ah1, ah2, ah3, bl0, bl1);
            mma16816(c[nt], al0, al1, al2, al3, bh0, bh1);
        }
    }

    size_t row0 = gbase + r0, row1 = row0 + 8;
    __half2* h16r0 = (__half2*)(hl16 + row0 * CH);
    __half2* h16r1 = (__half2*)(hl16 + row1 * CH);
    #pragma unroll
    for (int nt = 0; nt < 8; nt++) {
        int col = nt * 8 + 2 * t4;
        float b0 = sb[col], b1 = sb[col + 1];
        float s00 = silu(c[nt][0] + b0), s01 = silu(c[nt][1] + b1);
        float s10 = silu(c[nt][2] + b0), s11 = silu(c[nt][3] + b1);
        *(float2*)(hdst + row0 * CH + col) = make_float2(s00, s01);
        *(float2*)(hdst + row1 * CH + col) = make_float2(s10, s11);
        h16r0[col >> 1] = __floats2half2_rn(s00, s01);
        h16r1[col >> 1] = __floats2half2_rn(s10, s11);
    }
}

// ---------------- readout ----------------
#define W1T_STRIDE 132   // floats; 528B, 16B-aligned
__global__ void __launch_bounds__(128) readout_kernel(
    const float* __restrict__ hl,
    const float* __restrict__ w1, const float* __restrict__ b1,
    const float* __restrict__ w2, const float* __restrict__ b2,
    float* __restrict__ out)
{
    extern __shared__ __align__(16) float smem[];
    float* sW1T = smem;                       // [128][132] transposed, padded
    float* sb1  = smem + 128 * W1T_STRIDE;
    float* sW2  = sb1 + 128;
    float* sb2  = sW2 + 256;
    for (int t = threadIdx.x; t < 128 * 128; t += 128) {
        int i = t >> 7, k = t & 127;
        sW1T[k * W1T_STRIDE + i] = w1[t];     // w1[i][k]
    }
    sb1[threadIdx.x] = b1[threadIdx.x];
    for (int t = threadIdx.x; t < 256; t += 128) sW2[t] = w2[t];
    if (threadIdx.x < 2) sb2[threadIdx.x] = b2[threadIdx.x];
    __syncthreads();
    uint32_t swa = (uint32_t)__cvta_generic_to_shared(sW1T);

    int v = blockIdx.x * 128 + threadIdx.x;
    if (v >= NVAR) return;

    u64 hv2[64];
    const float4* hp = (const float4*)(hl + (size_t)v * 128);
    #pragma unroll
    for (int j = 0; j < 32; j++) {
        float4 h = __ldg(hp + j);
        hv2[2 * j]     = pack2(h.x, h.y);
        hv2[2 * j + 1] = pack2(h.z, h.w);
    }

    float y0 = sb2[0], y1 = sb2[1];
    #pragma unroll 2
    for (int k = 0; k < 128; k++) {
        u64 t0 = 0, t1 = 0, t2 = 0, t3 = 0;
        uint32_t ra = swa + k * (W1T_STRIDE * 4);
        #pragma unroll
        for (int j = 0; j < 32; j++) {
            u64 w0, w1v;
            lds_v2u64(w0, w1v, ra + (j << 4));
            fma2((j & 1) ? t1 : t0, hv2[2 * j],     w0);
            fma2((j & 1) ? t3 : t2, hv2[2 * j + 1], w1v);
        }
        float2 a = unpack2(t0), bq = unpack2(t1), c = unpack2(t2), d = unpack2(t3);
        float t = ((a.x + a.y) + (bq.x + bq.y)) + ((c.x + c.y) + (d.x + d.y)) + sb1[k];
        float s = silu(t);
        y0 += s * sW2[2 * k];
        y1 += s * sW2[2 * k + 1];
    }
    out[2 * v]     = y0;
    out[2 * v + 1] = y1;
}

// ---------------- launcher ----------------
extern "C" void kernel_launch(void* const* d_in, const int* in_sizes, int n_in,
                              void* d_out, int out_size)
{
    const float* x_lit  = (const float*)d_in[0];
    const float* x_cls  = (const float*)d_in[1];
    const int*   e_lit  = (const int*)  d_in[2];
    const int*   e_cls  = (const int*)  d_in[3];
    const float* enc_w1 = (const float*)d_in[4];
    const float* enc_b1 = (const float*)d_in[5];
    const float* enc_w2 = (const float*)d_in[6];
    const float* enc_b2 = (const float*)d_in[7];
    const float* Wc     = (const float*)d_in[8];
    const float* bc     = (const float*)d_in[9];
    const float* Wl     = (const float*)d_in[10];
    const float* bl     = (const float*)d_in[11];
    const float* out_w1 = (const float*)d_in[12];
    const float* out_b1 = (const float*)d_in[13];
    const float* out_w2 = (const float*)d_in[14];
    const float* out_b2 = (const float*)d_in[15];
    float* y = (float*)d_out;

    float *p_hlA, *p_hlB, *p_hc, *p_m, *p_inv;
    __half *p_hl16, *p_hc16;
    int *p_cnt, *p_rs, *p_cur, *p_adj;
    cudaGetSymbolAddress((void**)&p_hlA, g_hlA);
    cudaGetSymbolAddress((void**)&p_hlB, g_hlB);
    cudaGetSymbolAddress((void**)&p_hc,  g_hc);
    cudaGetSymbolAddress((void**)&p_m,   g_m);
    cudaGetSymbolAddress((void**)&p_hl16, g_hl16);
    cudaGetSymbolAddress((void**)&p_hc16, g_hc16);
    cudaGetSymbolAddress((void**)&p_cnt, g_cnt);
    cudaGetSymbolAddress((void**)&p_inv, g_inv);
    cudaGetSymbolAddress((void**)&p_rs,  g_rs);
    cudaGetSymbolAddress((void**)&p_cur, g_cur);
    cudaGetSymbolAddress((void**)&p_adj, g_adj);

    const int smem_cls = (64 * AST * 2 + 64 * WST * 2 + 64) * 4;
    const int smem_lit = (64 * AST * 2 + 96 * WST * 2 + 64) * 4;
    cudaFuncSetAttribute(cls_update, cudaFuncAttributeMaxDynamicSharedMemorySize, smem_cls);
    cudaFuncSetAttribute(lit_update, cudaFuncAttributeMaxDynamicSharedMemorySize, smem_lit);
    cudaFuncSetAttribute(readout_kernel, cudaFuncAttributeMaxDynamicSharedMemorySize,
                         (128 * W1T_STRIDE + 128 + 256 + 8) * 4);

    // 1) encoder + edge counting (cnt/tiles/ctr reset by previous call's fill / static init)
    encoder_kernel<<<(NT + 127) / 128, 128>>>(
        x_lit, x_cls, enc_w1, enc_b1, enc_w2, enc_b2,
        e_lit, e_cls, p_cnt, p_hlA, p_hc, p_hl16, p_hc16);

    // 2) single-pass scan -> rs, cur, inv
    int nb = (NT + SCAN_B - 1) / SCAN_B;
    scan_onepass<<<nb, SCAN_B>>>(p_cnt, p_rs, p_cur, p_inv, NT);

    // 3) adjacency fill + reset cnt/scan state
    fill_kernel<<<(NE + 255) / 256, 256>>>(e_lit, e_cls, p_cur, p_adj, p_cnt);

    // 4+) message-passing layers — gathers read fp16 shadows (hl16 26MB, hc16 102MB; both < L2)
    float* cur = p_hlA;
    float* nxt = p_hlB;
    for (int l = 0; l < NLAY; l++) {
        agg_kernel<<<((size_t)N_CLS * 32 + 255) / 256, 256>>>(
            p_hl16, p_rs, p_adj, p_inv, p_m, N_CLS);
        cls_update<<<N_CLS / 64, 128, smem_cls>>>(
            p_hc, p_m, Wc + (size_t)l * 2 * CH * CH, bc + l * CH, p_hc16);
        agg_kernel<<<((size_t)N_LIT * 32 + 255) / 256, 256>>>(
            p_hc16, p_rs + N_CLS, p_adj, p_inv + N_CLS, p_m, N_LIT);
        lit_update<<<N_LIT / 64, 128, smem_lit>>>(
            cur, nxt, p_m, Wl + (size_t)l * 3 * CH * CH, bl + l * CH, p_hl16);
        float* tmp = cur; cur = nxt; nxt = tmp;
    }

    // readout (fp32 path)
    readout_kernel<<<(NVAR + 127) / 128, 128, (128 * W1T_STRIDE + 128 + 256 + 8) * 4>>>(
        cur, out_w1, out_b1, out_w2, out_b2, y);
}

// round 16
// speedup vs baseline: 1.4525x; 1.3075x over previous
#include <cuda_runtime.h>
#include <cuda_bf16.h>
#include <cuda_fp16.h>
#include <cstddef>
#include <cstdint>

#define N_LIT 200000
#define N_CLS 800000
#define NE    2400000
#define NT    (N_CLS + N_LIT)
#define CH    64
#define NVAR  (N_LIT/2)
#define NLAY  4
#define SCAN_B 1024

typedef unsigned long long u64;

// ---------------- device scratch (static, no allocation) ----------------
// All node state and messages live in fp16 (error budget: rel_err limit 1e-3).
__device__ __half g_hlA16[(size_t)N_LIT * CH];
__device__ __half g_hlB16[(size_t)N_LIT * CH];
__device__ __half g_hc16 [(size_t)N_CLS * CH];
__device__ __half g_m16  [(size_t)N_CLS * CH];
__device__ int   g_cnt[NT];          // zero-init; re-zeroed by fill_kernel each call
__device__ float g_inv[NT];
__device__ int   g_rs [NT + 1];
__device__ int   g_cur[NT];
__device__ int   g_adj[2 * NE];      // [0,NE): lits by clause; [NE,2NE): clauses by literal
__device__ u64   g_tiles[1024];      // decoupled-lookback state
__device__ unsigned int g_ctr;       // ticket counter

__device__ __forceinline__ float silu(float x) { return x / (1.0f + __expf(-x)); }

// ---- f32x2 packed helpers (encoder/readout scalar path) ----
__device__ __forceinline__ u64 pack2(float lo, float hi) {
    u64 r; asm("mov.b64 %0, {%1,%2};" : "=l"(r) : "f"(lo), "f"(hi)); return r;
}
__device__ __forceinline__ u64 pack_dup(float x) {
    u64 r; asm("mov.b64 %0, {%1,%1};" : "=l"(r) : "f"(x)); return r;
}
__device__ __forceinline__ void fma2(u64& acc, u64 a, u64 b) {
    asm("fma.rn.f32x2 %0, %1, %2, %0;" : "+l"(acc) : "l"(a), "l"(b));
}
__device__ __forceinline__ float2 unpack2(u64 v) {
    float2 f; asm("mov.b64 {%0,%1}, %2;" : "=f"(f.x), "=f"(f.y) : "l"(v)); return f;
}
__device__ __forceinline__ void lds_v2u64(u64& a, u64& b, uint32_t addr) {
    asm("ld.shared.v2.b64 {%0,%1}, [%2];" : "=l"(a), "=l"(b) : "r"(addr));
}

// ---- cache-policy memory helpers ----
__device__ __forceinline__ u64 make_policy_evict_last() {
    u64 pol;
    asm("createpolicy.fractional.L2::evict_last.b64 %0, 1.0;" : "=l"(pol));
    return pol;
}
__device__ __forceinline__ uint32_t ldg_hint_u32(const uint32_t* p, u64 pol) {
    uint32_t v;
    asm("ld.global.nc.L2::cache_hint.b32 %0, [%1], %2;" : "=r"(v) : "l"(p), "l"(pol));
    return v;
}
__device__ __forceinline__ void stg_cs_u32(uint32_t* p, uint32_t v) {
    asm volatile("st.global.cs.b32 [%0], %1;" :: "l"(p), "r"(v) : "memory");
}
__device__ __forceinline__ uint32_t ldg_cs_u32(const uint32_t* p) {
    uint32_t v;
    asm("ld.global.cs.b32 %0, [%1];" : "=r"(v) : "l"(p));
    return v;
}
__device__ __forceinline__ float2 h2f2(uint32_t u) {
    __half2 h;
    *reinterpret_cast<uint32_t*>(&h) = u;
    return __half22float2(h);
}

// ---- W split-pack: w = hi + lo, both fp16, packed fp16x2 along k ----
__device__ __forceinline__ void splitw(float x0, float x1, uint32_t& hi, uint32_t& lo) {
    __half h0 = __float2half_rn(x0);
    __half h1 = __float2half_rn(x1);
    float r0 = x0 - __half2float(h0);
    float r1 = x1 - __half2float(h1);
    __half l0 = __float2half_rn(r0);
    __half l1 = __float2half_rn(r1);
    hi = ((uint32_t)__half_as_ushort(h1) << 16) | (uint32_t)__half_as_ushort(h0);
    lo = ((uint32_t)__half_as_ushort(l1) << 16) | (uint32_t)__half_as_ushort(l0);
}

// fp16 m16n8k16 MMA, fp32 accumulate
__device__ __forceinline__ void mma16816(float* c,
    uint32_t a0, uint32_t a1, uint32_t a2, uint32_t a3, uint32_t b0, uint32_t b1)
{
    asm("mma.sync.aligned.m16n8k16.row.col.f32.f16.f16.f32 "
        "{%0,%1,%2,%3}, {%4,%5,%6,%7}, {%8,%9}, {%0,%1,%2,%3};"
        : "+f"(c[0]), "+f"(c[1]), "+f"(c[2]), "+f"(c[3])
        : "r"(a0), "r"(a1), "r"(a2), "r"(a3), "r"(b0), "r"(b1));
}

// ---------------- 1) encoder + edge counting (fused), fp16 outputs ----------------
__global__ void __launch_bounds__(128) encoder_kernel(
    const float* __restrict__ xl, const float* __restrict__ xc,
    const float* __restrict__ w1, const float* __restrict__ b1,
    const float* __restrict__ w2, const float* __restrict__ b2,
    const int* __restrict__ el, const int* __restrict__ ec,
    int* __restrict__ cnt,
    __half* __restrict__ hl16, __half* __restrict__ hc16)
{
    __shared__ __align__(16) float sW1[4 * CH];
    __shared__ __align__(16) float sb1[CH];
    __shared__ __align__(16) float sW2[CH * CH];
    __shared__ __align__(16) float sb2[CH];
    for (int t = threadIdx.x; t < 64; t += 128) ((float4*)sW1)[t] = ((const float4*)w1)[t];
    for (int t = threadIdx.x; t < CH * 16; t += 128) ((float4*)sW2)[t] = ((const float4*)w2)[t];
    if (threadIdx.x < CH) { sb1[threadIdx.x] = b1[threadIdx.x]; sb2[threadIdx.x] = b2[threadIdx.x]; }
    __syncthreads();
    uint32_t sw2a = (uint32_t)__cvta_generic_to_shared(sW2);

    int i = blockIdx.x * 128 + threadIdx.x;
    int stride = gridDim.x * 128;

    for (size_t e = i; e < NE; e += stride) {
        atomicAdd(cnt + __ldg(ec + e), 1);
        atomicAdd(cnt + N_CLS + __ldg(el + e), 1);
    }

    if (i >= NT) return;
    const float* x;
    __half* out16;
    if (i < N_LIT) { x = xl + (size_t)i * 4;           out16 = hl16 + (size_t)i * CH; }
    else           { x = xc + (size_t)(i - N_LIT) * 4; out16 = hc16 + (size_t)(i - N_LIT) * CH; }
    float4 xv = __ldg((const float4*)x);

    u64 acc2[32];
    #pragma unroll
    for (int j = 0; j < 16; j++) {
        float4 bv = ((const float4*)sb2)[j];
        acc2[2 * j]     = pack2(bv.x, bv.y);
        acc2[2 * j + 1] = pack2(bv.z, bv.w);
    }

    #pragma unroll 8
    for (int k = 0; k < CH; k++) {
        float t = sb1[k] + xv.x * sW1[k] + xv.y * sW1[CH + k] + xv.z * sW1[2 * CH + k] + xv.w * sW1[3 * CH + k];
        u64 s2 = pack_dup(silu(t));
        uint32_t ra = sw2a + (k << 8);
        #pragma unroll
        for (int j = 0; j < 16; j++) {
            u64 w0, w1v;
            lds_v2u64(w0, w1v, ra + (j << 4));
            fma2(acc2[2 * j],     s2, w0);
            fma2(acc2[2 * j + 1], s2, w1v);
        }
    }
    __half2* o16 = (__half2*)out16;
    #pragma unroll
    for (int j = 0; j < 16; j++) {
        float2 a = unpack2(acc2[2 * j]);
        float2 b = unpack2(acc2[2 * j + 1]);
        o16[2 * j]     = __floats2half2_rn(a.x, a.y);
        o16[2 * j + 1] = __floats2half2_rn(b.x, b.y);
    }
}

// ---------------- 2) single-pass scan (decoupled lookback, ticket-ordered) ----------------
__global__ void __launch_bounds__(SCAN_B) scan_onepass(
    const int* __restrict__ cnt, int* __restrict__ rs, int* __restrict__ cur,
    float* __restrict__ inv, int n)
{
    __shared__ int s[SCAN_B];
    __shared__ int sbid;
    __shared__ int sbase;
    if (threadIdx.x == 0) sbid = (int)atomicAdd(&g_ctr, 1u);
    __syncthreads();
    int bid = sbid;
    int i = bid * SCAN_B + threadIdx.x;
    int v = (i < n) ? cnt[i] : 0;
    s[threadIdx.x] = v;
    __syncthreads();
    for (int off = 1; off < SCAN_B; off <<= 1) {
        int t = (threadIdx.x >= off) ? s[threadIdx.x - off] : 0;
        __syncthreads();
        s[threadIdx.x] += t;
        __syncthreads();
    }
    if (threadIdx.x == 0) {
        int total = s[SCAN_B - 1];
        if (bid == 0) {
            atomicExch(&g_tiles[0], (2ull << 32) | (unsigned)total);
            sbase = 0;
        } else {
            atomicExch(&g_tiles[bid], (1ull << 32) | (unsigned)total);
            int base = 0;
            int t = bid - 1;
            while (t >= 0) {
                u64 st;
                do { st = atomicAdd(&g_tiles[t], 0ull); } while ((st >> 32) == 0ull);
                base += (int)(unsigned)st;
                if ((st >> 32) == 2ull) break;
                t--;
            }
            atomicExch(&g_tiles[bid], (2ull << 32) | (unsigned)(base + total));
            sbase = base;
        }
    }
    __syncthreads();
    int base = sbase;
    if (i < n) {
        int r = base + s[threadIdx.x] - v;
        rs[i] = r;
        cur[i] = r;
        inv[i] = (v > 0) ? (1.0f / (float)v) : 1.0f;
    }
    if (bid == 0 && threadIdx.x == 0) rs[n] = 2 * NE;
}

// ---------------- 3) adjacency fill (+ reset cnt / scan state for next call) ----------------
__global__ void fill_kernel(const int* __restrict__ el, const int* __restrict__ ec,
                            int* __restrict__ cur, int* __restrict__ adj,
                            int* __restrict__ cnt) {
    int e = blockIdx.x * 256 + threadIdx.x;
    if (e < NT) cnt[e] = 0;
    if (e < 1024) g_tiles[e] = 0ull;
    if (e == 0) g_ctr = 0u;
    if (e < NE) {
        int l = __ldg(el + e), c = __ldg(ec + e);
        adj[atomicAdd(cur + c, 1)]         = l;
        adj[atomicAdd(cur + N_CLS + l, 1)] = c;
    }
}

// ---------------- aggregation: warp-per-node, fp16 source + fp16 dest ----------------
__global__ void __launch_bounds__(256) agg_kernel(
    const __half* __restrict__ src, const int* __restrict__ rs,
    const int* __restrict__ adj, const float* __restrict__ inv,
    __half* __restrict__ m, int n)
{
    int w = (blockIdx.x * 256 + threadIdx.x) >> 5;
    if (w >= n) return;
    int lane = threadIdx.x & 31;
    u64 pol = make_policy_evict_last();
    int start = __ldg(rs + w), end = __ldg(rs + w + 1);
    const uint32_t* base = (const uint32_t*)src;
    float ax = 0.f, ay = 0.f;
    for (int p0 = start; p0 < end; p0 += 4) {
        int r = end - p0;                                  // >= 1
        int j0 = __ldg(adj + p0);
        int j1 = (r > 1) ? __ldg(adj + p0 + 1) : j0;
        int j2 = (r > 2) ? __ldg(adj + p0 + 2) : j0;
        int j3 = (r > 3) ? __ldg(adj + p0 + 3) : j0;
        uint32_t u0 = ldg_hint_u32(base + (size_t)j0 * 32 + lane, pol);
        uint32_t u1 = ldg_hint_u32(base + (size_t)j1 * 32 + lane, pol);
        uint32_t u2 = ldg_hint_u32(base + (size_t)j2 * 32 + lane, pol);
        uint32_t u3 = ldg_hint_u32(base + (size_t)j3 * 32 + lane, pol);
        float2 v0 = h2f2(u0), v1 = h2f2(u1), v2 = h2f2(u2), v3 = h2f2(u3);
        float m1 = (r > 1) ? 1.f : 0.f;
        float m2 = (r > 2) ? 1.f : 0.f;
        float m3 = (r > 3) ? 1.f : 0.f;
        ax += v0.x + m1 * v1.x + m2 * v2.x + m3 * v3.x;
        ay += v0.y + m1 * v1.y + m2 * v2.y + m3 * v3.y;
    }
    float iv = __ldg(inv + w);
    __half2 o = __floats2half2_rn(ax * iv, ay * iv);
    stg_cs_u32((uint32_t*)m + (size_t)w * 32 + lane, *(uint32_t*)&o);
}

// ================= f16 HMMA update kernels =================
// A tile: fp16x2 u32 directly from gmem (no conversion). W: fp16 hi + fp16 residual.
// D = A @ (Wh + Wl): 2 MMAs per tile.
#define AST 68
#define WST 72

// ---- cls: hc16 = silu([hc16, m16] @ Wc + bc), K=128, in place ----
__global__ void __launch_bounds__(128) cls_update(
    __half* __restrict__ hc16, const __half* __restrict__ m16,
    const float* __restrict__ W, const float* __restrict__ b)
{
    extern __shared__ uint32_t smu[];
    uint32_t* sA  = smu;                   // 64*68 (self pairs 0..31, m pairs 32..63)
    uint32_t* sWh = sA + 64 * AST;         // 64*72
    uint32_t* sWl = sWh + 64 * WST;
    float*    sb  = (float*)(sWl + 64 * WST);

    int tid = threadIdx.x;
    size_t gbase = (size_t)blockIdx.x * 64;

    for (int idx = tid; idx < 64 * 64; idx += 128) {
        int p = idx >> 6, c = idx & 63;
        float w0 = __ldg(W + (size_t)(2 * p) * 64 + c);
        float w1 = __ldg(W + (size_t)(2 * p + 1) * 64 + c);
        uint32_t hi, lo; splitw(w0, w1, hi, lo);
        sWh[p * WST + c] = hi; sWl[p * WST + c] = lo;
    }
    const uint32_t* hcu = (const uint32_t*)hc16;
    const uint32_t* mu  = (const uint32_t*)m16;
    for (int idx = tid; idx < 64 * 32; idx += 128) {
        int nd = idx >> 5, pj = idx & 31;
        sA[nd * AST + pj]      = __ldg(hcu + (gbase + nd) * 32 + pj);
        sA[nd * AST + 32 + pj] = ldg_cs_u32(mu + (gbase + nd) * 32 + pj);
    }
    if (tid < 64) sb[tid] = b[tid];
    __syncthreads();

    int lane = tid & 31, warp = tid >> 5;
    int g = lane >> 2, t4 = lane & 3;
    int r0 = warp * 16 + g;

    float c[8][4];
    #pragma unroll
    for (int nt = 0; nt < 8; nt++) { c[nt][0] = c[nt][1] = c[nt][2] = c[nt][3] = 0.f; }

    #pragma unroll
    for (int s = 0; s < 8; s++) {
        int pb = s * 8 + t4;
        uint32_t a0 = sA[r0 * AST + pb],       a1 = sA[(r0 + 8) * AST + pb];
        uint32_t a2 = sA[r0 * AST + pb + 4],   a3 = sA[(r0 + 8) * AST + pb + 4];
        #pragma unroll
        for (int nt = 0; nt < 8; nt++) {
            int wc = nt * 8 + g;
            uint32_t bh0 = sWh[pb * WST + wc], bh1 = sWh[(pb + 4) * WST + wc];
            uint32_t bl0 = sWl[pb * WST + wc], bl1 = sWl[(pb + 4) * WST + wc];
            mma16816(c[nt], a0, a1, a2, a3, bh0, bh1);
            mma16816(c[nt], a0, a1, a2, a3, bl0, bl1);
        }
    }

    size_t row0 = gbase + r0, row1 = row0 + 8;
    __half2* h16r0 = (__half2*)(hc16 + row0 * CH);
    __half2* h16r1 = (__half2*)(hc16 + row1 * CH);
    #pragma unroll
    for (int nt = 0; nt < 8; nt++) {
        int col = nt * 8 + 2 * t4;
        float b0 = sb[col], b1 = sb[col + 1];
        h16r0[col >> 1] = __floats2half2_rn(silu(c[nt][0] + b0), silu(c[nt][1] + b1));
        h16r1[col >> 1] = __floats2half2_rn(silu(c[nt][2] + b0), silu(c[nt][3] + b1));
    }
}

// ---- lit: hdst16 = silu([hsrc16, m16, hsrc16_flip] @ Wl + bl), K=192 ----
__global__ void __launch_bounds__(128) lit_update(
    const __half* __restrict__ hsrc16, __half* __restrict__ hdst16,
    const __half* __restrict__ m16,
    const float* __restrict__ W, const float* __restrict__ b)
{
    extern __shared__ uint32_t smu[];
    uint32_t* sA  = smu;                   // 64*68 (self pairs 0..31, m pairs 32..63)
    uint32_t* sWh = sA + 64 * AST;         // 96*72
    uint32_t* sWl = sWh + 96 * WST;
    float*    sb  = (float*)(sWl + 96 * WST);

    int tid = threadIdx.x;
    size_t gbase = (size_t)blockIdx.x * 64;

    for (int idx = tid; idx < 96 * 64; idx += 128) {
        int p = idx >> 6, c = idx & 63;
        float w0 = __ldg(W + (size_t)(2 * p) * 64 + c);
        float w1 = __ldg(W + (size_t)(2 * p + 1) * 64 + c);
        uint32_t hi, lo; splitw(w0, w1, hi, lo);
        sWh[p * WST + c] = hi; sWl[p * WST + c] = lo;
    }
    const uint32_t* hsu = (const uint32_t*)hsrc16;
    const uint32_t* mu  = (const uint32_t*)m16;
    for (int idx = tid; idx < 64 * 32; idx += 128) {
        int nd = idx >> 5, pj = idx & 31;
        sA[nd * AST + pj]      = __ldg(hsu + (gbase + nd) * 32 + pj);
        sA[nd * AST + 32 + pj] = ldg_cs_u32(mu + (gbase + nd) * 32 + pj);
    }
    if (tid < 64) sb[tid] = b[tid];
    __syncthreads();

    int lane = tid & 31, warp = tid >> 5;
    int g = lane >> 2, t4 = lane & 3;
    int r0 = warp * 16 + g;

    float c[8][4];
    #pragma unroll
    for (int nt = 0; nt < 8; nt++) { c[nt][0] = c[nt][1] = c[nt][2] = c[nt][3] = 0.f; }

    // segments 1+2: self + m (A pairs 0..63, W pairs 0..63)
    #pragma unroll
    for (int s = 0; s < 8; s++) {
        int pb = s * 8 + t4;
        uint32_t a0 = sA[r0 * AST + pb],       a1 = sA[(r0 + 8) * AST + pb];
        uint32_t a2 = sA[r0 * AST + pb + 4],   a3 = sA[(r0 + 8) * AST + pb + 4];
        #pragma unroll
        for (int nt = 0; nt < 8; nt++) {
            int wc = nt * 8 + g;
            uint32_t bh0 = sWh[pb * WST + wc], bh1 = sWh[(pb + 4) * WST + wc];
            uint32_t bl0 = sWl[pb * WST + wc], bl1 = sWl[(pb + 4) * WST + wc];
            mma16816(c[nt], a0, a1, a2, a3, bh0, bh1);
            mma16816(c[nt], a0, a1, a2, a3, bl0, bl1);
        }
    }
    // segment 3: flip (A = self of node^1, pairs 0..31; W pairs 64..95)
    int f0 = r0 ^ 1, f1 = (r0 + 8) ^ 1;
    #pragma unroll
    for (int s = 0; s < 4; s++) {
        int pa = s * 8 + t4;
        int pw = 64 + s * 8 + t4;
        uint32_t a0 = sA[f0 * AST + pa],       a1 = sA[f1 * AST + pa];
        uint32_t a2 = sA[f0 * AST + pa + 4],   a3 = sA[f1 * AST + pa + 4];
        #pragma unroll
        for (int nt = 0; nt < 8; nt++) {
            int wc = nt * 8 + g;
            uint32_t bh0 = sWh[pw * WST + wc], bh1 = sWh[(pw + 4) * WST + wc];
            uint32_t bl0 = sWl[pw * WST + wc], bl1 = sWl[(pw + 4) * WST + wc];
            mma16816(c[nt], a0, a1, a2, a3, bh0, bh1);
            mma16816(c[nt], a0, a1, a2, a3, bl0, bl1);
        }
    }

    size_t row0 = gbase + r0, row1 = row0 + 8;
    __half2* h16r0 = (__half2*)(hdst16 + row0 * CH);
    __half2* h16r1 = (__half2*)(hdst16 + row1 * CH);
    #pragma unroll
    for (int nt = 0; nt < 8; nt++) {
        int col = nt * 8 + 2 * t4;
        float b0 = sb[col], b1 = sb[col + 1];
        h16r0[col >> 1] = __floats2half2_rn(silu(c[nt][0] + b0), silu(c[nt][1] + b1));
        h16r1[col >> 1] = __floats2half2_rn(silu(c[nt][2] + b0), silu(c[nt][3] + b1));
    }
}

// ---------------- readout (fp16 input, fp32 math) ----------------
#define W1T_STRIDE 132   // floats; 528B, 16B-aligned
__global__ void __launch_bounds__(128) readout_kernel(
    const __half* __restrict__ hl16,
    const float* __restrict__ w1, const float* __restrict__ b1,
    const float* __restrict__ w2, const float* __restrict__ b2,
    float* __restrict__ out)
{
    extern __shared__ __align__(16) float smem[];
    float* sW1T = smem;                       // [128][132] transposed, padded
    float* sb1  = smem + 128 * W1T_STRIDE;
    float* sW2  = sb1 + 128;
    float* sb2  = sW2 + 256;
    for (int t = threadIdx.x; t < 128 * 128; t += 128) {
        int i = t >> 7, k = t & 127;
        sW1T[k * W1T_STRIDE + i] = w1[t];     // w1[i][k]
    }
    sb1[threadIdx.x] = b1[threadIdx.x];
    for (int t = threadIdx.x; t < 256; t += 128) sW2[t] = w2[t];
    if (threadIdx.x < 2) sb2[threadIdx.x] = b2[threadIdx.x];
    __syncthreads();
    uint32_t swa = (uint32_t)__cvta_generic_to_shared(sW1T);

    int v = blockIdx.x * 128 + threadIdx.x;
    if (v >= NVAR) return;

    u64 hv2[64];
    const uint32_t* hp = (const uint32_t*)(hl16 + (size_t)v * 128);
    #pragma unroll
    for (int j = 0; j < 64; j++) {
        float2 f = h2f2(__ldg(hp + j));
        hv2[j] = pack2(f.x, f.y);
    }

    float y0 = sb2[0], y1 = sb2[1];
    #pragma unroll 2
    for (int k = 0; k < 128; k++) {
        u64 t0 = 0, t1 = 0, t2 = 0, t3 = 0;
        uint32_t ra = swa + k * (W1T_STRIDE * 4);
        #pragma unroll
        for (int j = 0; j < 32; j++) {
            u64 w0, w1v;
            lds_v2u64(w0, w1v, ra + (j << 4));
            fma2((j & 1) ? t1 : t0, hv2[2 * j],     w0);
            fma2((j & 1) ? t3 : t2, hv2[2 * j + 1], w1v);
        }
        float2 a = unpack2(t0), bq = unpack2(t1), c = unpack2(t2), d = unpack2(t3);
        float t = ((a.x + a.y) + (bq.x + bq.y)) + ((c.x + c.y) + (d.x + d.y)) + sb1[k];
        float s = silu(t);
        y0 += s * sW2[2 * k];
        y1 += s * sW2[2 * k + 1];
    }
    out[2 * v]     = y0;
    out[2 * v + 1] = y1;
}

// ---------------- launcher ----------------
extern "C" void kernel_launch(void* const* d_in, const int* in_sizes, int n_in,
                              void* d_out, int out_size)
{
    const float* x_lit  = (const float*)d_in[0];
    const float* x_cls  = (const float*)d_in[1];
    const int*   e_lit  = (const int*)  d_in[2];
    const int*   e_cls  = (const int*)  d_in[3];
    const float* enc_w1 = (const float*)d_in[4];
    const float* enc_b1 = (const float*)d_in[5];
    const float* enc_w2 = (const float*)d_in[6];
    const float* enc_b2 = (const float*)d_in[7];
    const float* Wc     = (const float*)d_in[8];
    const float* bc     = (const float*)d_in[9];
    const float* Wl     = (const float*)d_in[10];
    const float* bl     = (const float*)d_in[11];
    const float* out_w1 = (const float*)d_in[12];
    const float* out_b1 = (const float*)d_in[13];
    const float* out_w2 = (const float*)d_in[14];
    const float* out_b2 = (const float*)d_in[15];
    float* y = (float*)d_out;

    __half *p_hlA16, *p_hlB16, *p_hc16, *p_m16;
    float *p_inv;
    int *p_cnt, *p_rs, *p_cur, *p_adj;
    cudaGetSymbolAddress((void**)&p_hlA16, g_hlA16);
    cudaGetSymbolAddress((void**)&p_hlB16, g_hlB16);
    cudaGetSymbolAddress((void**)&p_hc16,  g_hc16);
    cudaGetSymbolAddress((void**)&p_m16,   g_m16);
    cudaGetSymbolAddress((void**)&p_cnt, g_cnt);
    cudaGetSymbolAddress((void**)&p_inv, g_inv);
    cudaGetSymbolAddress((void**)&p_rs,  g_rs);
    cudaGetSymbolAddress((void**)&p_cur, g_cur);
    cudaGetSymbolAddress((void**)&p_adj, g_adj);

    const int smem_cls = (64 * AST + 2 * 64 * WST + 64) * 4;   // 54,528 B
    const int smem_lit = (64 * AST + 2 * 96 * WST + 64) * 4;   // 72,960 B
    cudaFuncSetAttribute(cls_update, cudaFuncAttributeMaxDynamicSharedMemorySize, smem_cls);
    cudaFuncSetAttribute(lit_update, cudaFuncAttributeMaxDynamicSharedMemorySize, smem_lit);
    cudaFuncSetAttribute(readout_kernel, cudaFuncAttributeMaxDynamicSharedMemorySize,
                         (128 * W1T_STRIDE + 128 + 256 + 8) * 4);

    // 1) encoder + edge counting (cnt/tiles/ctr reset by previous call's fill / static init)
    encoder_kernel<<<(NT + 127) / 128, 128>>>(
        x_lit, x_cls, enc_w1, enc_b1, enc_w2, enc_b2,
        e_lit, e_cls, p_cnt, p_hlA16, p_hc16);

    // 2) single-pass scan -> rs, cur, inv
    int nb = (NT + SCAN_B - 1) / SCAN_B;
    scan_onepass<<<nb, SCAN_B>>>(p_cnt, p_rs, p_cur, p_inv, NT);

    // 3) adjacency fill + reset cnt/scan state
    fill_kernel<<<(NE + 255) / 256, 256>>>(e_lit, e_cls, p_cur, p_adj, p_cnt);

    // 4+) message-passing layers (all state fp16)
    __half* cur16 = p_hlA16;
    __half* nxt16 = p_hlB16;
    for (int l = 0; l < NLAY; l++) {
        agg_kernel<<<((size_t)N_CLS * 32 + 255) / 256, 256>>>(
            cur16, p_rs, p_adj, p_inv, p_m16, N_CLS);
        cls_update<<<N_CLS / 64, 128, smem_cls>>>(
            p_hc16, p_m16, Wc + (size_t)l * 2 * CH * CH, bc + l * CH);
        agg_kernel<<<((size_t)N_LIT * 32 + 255) / 256, 256>>>(
            p_hc16, p_rs + N_CLS, p_adj, p_inv + N_CLS, p_m16, N_LIT);
        lit_update<<<N_LIT / 64, 128, smem_lit>>>(
            cur16, nxt16, p_m16, Wl + (size_t)l * 3 * CH * CH, bl + l * CH);
        __half* tmp = cur16; cur16 = nxt16; nxt16 = tmp;
    }

    // readout
    readout_kernel<<<(NVAR + 127) / 128, 128, (128 * W1T_STRIDE + 128 + 256 + 8) * 4>>>(
        cur16, out_w1, out_b1, out_w2, out_b2, y);
}

// round 17
// speedup vs baseline: 1.5834x; 1.0901x over previous
#include <cuda_runtime.h>
#include <cuda_bf16.h>
#include <cuda_fp16.h>
#include <cstddef>
#include <cstdint>

#define N_LIT 200000
#define N_CLS 800000
#define NE    2400000
#define NT    (N_CLS + N_LIT)
#define CH    64
#define NVAR  (N_LIT/2)
#define NLAY  4
#define SCAN_B 1024

typedef unsigned long long u64;

// ---------------- device scratch (static, no allocation) ----------------
__device__ __half g_hlA16[(size_t)N_LIT * CH];
__device__ __half g_hlB16[(size_t)N_LIT * CH];
__device__ __half g_hc16 [(size_t)N_CLS * CH];
__device__ __half g_m16  [(size_t)N_CLS * CH];
__device__ uint32_t g_wenc16[2 * 2048];           // enc W2 split: [hi 2048][lo 2048]
__device__ uint32_t g_wcls16[NLAY * 2 * 4096];    // per layer: [hi 4096][lo 4096]
__device__ uint32_t g_wlit16[NLAY * 2 * 6144];    // per layer: [hi 6144][lo 6144]
__device__ int   g_cnt[NT];          // zero-init; re-zeroed by fill_kernel each call
__device__ float g_inv[NT];
__device__ int   g_rs [NT + 1];
__device__ int   g_cur[NT];
__device__ int   g_adj[2 * NE];
__device__ u64   g_tiles[1024];
__device__ unsigned int g_ctr;

__device__ __forceinline__ float silu(float x) { return x / (1.0f + __expf(-x)); }

// ---- f32x2 packed helpers (readout scalar path) ----
__device__ __forceinline__ u64 pack2(float lo, float hi) {
    u64 r; asm("mov.b64 %0, {%1,%2};" : "=l"(r) : "f"(lo), "f"(hi)); return r;
}
__device__ __forceinline__ void fma2(u64& acc, u64 a, u64 b) {
    asm("fma.rn.f32x2 %0, %1, %2, %0;" : "+l"(acc) : "l"(a), "l"(b));
}
__device__ __forceinline__ float2 unpack2(u64 v) {
    float2 f; asm("mov.b64 {%0,%1}, %2;" : "=f"(f.x), "=f"(f.y) : "l"(v)); return f;
}
__device__ __forceinline__ void lds_v2u64(u64& a, u64& b, uint32_t addr) {
    asm("ld.shared.v2.b64 {%0,%1}, [%2];" : "=l"(a), "=l"(b) : "r"(addr));
}

// ---- cache-policy memory helpers ----
__device__ __forceinline__ u64 make_policy_evict_last() {
    u64 pol;
    asm("createpolicy.fractional.L2::evict_last.b64 %0, 1.0;" : "=l"(pol));
    return pol;
}
__device__ __forceinline__ uint32_t ldg_hint_u32(const uint32_t* p, u64 pol) {
    uint32_t v;
    asm("ld.global.nc.L2::cache_hint.b32 %0, [%1], %2;" : "=r"(v) : "l"(p), "l"(pol));
    return v;
}
__device__ __forceinline__ void stg_cs_u32(uint32_t* p, uint32_t v) {
    asm volatile("st.global.cs.b32 [%0], %1;" :: "l"(p), "r"(v) : "memory");
}
__device__ __forceinline__ uint32_t ldg_cs_u32(const uint32_t* p) {
    uint32_t v;
    asm("ld.global.cs.b32 %0, [%1];" : "=r"(v) : "l"(p));
    return v;
}
__device__ __forceinline__ float2 h2f2(uint32_t u) {
    __half2 h;
    *reinterpret_cast<uint32_t*>(&h) = u;
    return __half22float2(h);
}

// ---- W split-pack: w = hi + lo, both fp16, packed fp16x2 along k ----
__device__ __forceinline__ void splitw(float x0, float x1, uint32_t& hi, uint32_t& lo) {
    __half h0 = __float2half_rn(x0);
    __half h1 = __float2half_rn(x1);
    float r0 = x0 - __half2float(h0);
    float r1 = x1 - __half2float(h1);
    __half l0 = __float2half_rn(r0);
    __half l1 = __float2half_rn(r1);
    hi = ((uint32_t)__half_as_ushort(h1) << 16) | (uint32_t)__half_as_ushort(h0);
    lo = ((uint32_t)__half_as_ushort(l1) << 16) | (uint32_t)__half_as_ushort(l0);
}

// fp16 m16n8k16 MMA, fp32 accumulate
__device__ __forceinline__ void mma16816(float* c,
    uint32_t a0, uint32_t a1, uint32_t a2, uint32_t a3, uint32_t b0, uint32_t b1)
{
    asm("mma.sync.aligned.m16n8k16.row.col.f32.f16.f16.f32 "
        "{%0,%1,%2,%3}, {%4,%5,%6,%7}, {%8,%9}, {%0,%1,%2,%3};"
        : "+f"(c[0]), "+f"(c[1]), "+f"(c[2]), "+f"(c[3])
        : "r"(a0), "r"(a1), "r"(a2), "r"(a3), "r"(b0), "r"(b1));
}

// ---------------- 0) pre-split all weights into fp16 hi/lo (once per call) ----------------
// enc: 2048 pair-entries; cls: 4*4096; lit: 4*6144. Total 43008 threads.
__global__ void prep_weights(const float* __restrict__ ew2,
                             const float* __restrict__ Wc,
                             const float* __restrict__ Wl)
{
    int i = blockIdx.x * 256 + threadIdx.x;
    uint32_t hi, lo;
    if (i < 2048) {
        int p = i >> 6, c = i & 63;
        splitw(ew2[(size_t)(2 * p) * 64 + c], ew2[(size_t)(2 * p + 1) * 64 + c], hi, lo);
        g_wenc16[i] = hi; g_wenc16[2048 + i] = lo;
    } else if (i < 2048 + NLAY * 4096) {
        int j = i - 2048;
        int l = j >> 12, e = j & 4095;
        int p = e >> 6, c = e & 63;
        const float* W = Wc + (size_t)l * 2 * CH * CH;
        splitw(W[(size_t)(2 * p) * 64 + c], W[(size_t)(2 * p + 1) * 64 + c], hi, lo);
        g_wcls16[(size_t)l * 8192 + e] = hi;
        g_wcls16[(size_t)l * 8192 + 4096 + e] = lo;
    } else if (i < 2048 + NLAY * 4096 + NLAY * 6144) {
        int j = i - 2048 - NLAY * 4096;
        int l = j / 6144, e = j % 6144;
        int p = e >> 6, c = e & 63;
        const float* W = Wl + (size_t)l * 3 * CH * CH;
        splitw(W[(size_t)(2 * p) * 64 + c], W[(size_t)(2 * p + 1) * 64 + c], hi, lo);
        g_wlit16[(size_t)l * 12288 + e] = hi;
        g_wlit16[(size_t)l * 12288 + 6144 + e] = lo;
    }
}

// ---------------- 1) encoder (HMMA) + edge counting ----------------
// 64 nodes / 128 threads per block. A = silu(x@W1+b1) computed into fp16 smem tile.
#define ASTE 36
#define WST  72
__global__ void __launch_bounds__(128) encoder_kernel(
    const float* __restrict__ xl, const float* __restrict__ xc,
    const float* __restrict__ w1, const float* __restrict__ b1,
    const float* __restrict__ b2,
    const int* __restrict__ el, const int* __restrict__ ec,
    int* __restrict__ cnt,
    __half* __restrict__ hl16, __half* __restrict__ hc16)
{
    extern __shared__ uint32_t smu[];
    uint32_t* sA  = smu;                   // [64][36] fp16x2 pairs (K=64 -> 32 pairs)
    uint32_t* sWh = sA + 64 * ASTE;        // [32][72]
    uint32_t* sWl = sWh + 32 * WST;
    float*    sW1 = (float*)(sWl + 32 * WST);   // [4*64]
    float*    sb1 = sW1 + 4 * CH;
    float*    sb  = sb1 + CH;              // b2

    int tid = threadIdx.x;
    size_t gbase = (size_t)blockIdx.x * 64;

    // edge-degree counting (grid-stride)
    {
        size_t i0 = (size_t)blockIdx.x * 128 + tid;
        size_t stride = (size_t)gridDim.x * 128;
        for (size_t e = i0; e < NE; e += stride) {
            atomicAdd(cnt + __ldg(ec + e), 1);
            atomicAdd(cnt + N_CLS + __ldg(el + e), 1);
        }
    }

    // stage pre-split enc W2 (32 rows x 64 cols, hi+lo): 1024 uint4
    {
        const uint4* ws = (const uint4*)g_wenc16;
        for (int idx = tid; idx < 1024; idx += 128) {
            int half = idx >> 9;            // 0=hi, 1=lo
            int q = idx & 511;
            int p = q >> 4, w4 = q & 15;
            uint32_t* dst = half ? sWl : sWh;
            ((uint4*)(dst + p * WST))[w4] = ws[idx];
        }
    }
    for (int t = tid; t < 4 * CH; t += 128) sW1[t] = w1[t];
    if (tid < CH) { sb1[tid] = b1[tid]; sb[tid] = b2[tid]; }
    __syncthreads();

    // compute s = silu(x@W1+b1), write fp16 pairs to sA; thread = (node nd, k-half)
    {
        int nd = tid & 63, half = tid >> 6;
        size_t n = gbase + nd;
        const float* x = (n < N_LIT) ? (xl + n * 4) : (xc + (n - N_LIT) * 4);
        float4 xv = __ldg((const float4*)x);
        int kb = half * 32;
        #pragma unroll
        for (int j = 0; j < 16; j++) {
            int k0 = kb + 2 * j, k1 = k0 + 1;
            float t0 = sb1[k0] + xv.x * sW1[k0] + xv.y * sW1[CH + k0] + xv.z * sW1[2 * CH + k0] + xv.w * sW1[3 * CH + k0];
            float t1 = sb1[k1] + xv.x * sW1[k1] + xv.y * sW1[CH + k1] + xv.z * sW1[2 * CH + k1] + xv.w * sW1[3 * CH + k1];
            __half2 s2 = __floats2half2_rn(silu(t0), silu(t1));
            sA[nd * ASTE + half * 16 + j] = *(uint32_t*)&s2;
        }
    }
    __syncthreads();

    int lane = tid & 31, warp = tid >> 5;
    int g = lane >> 2, t4 = lane & 3;
    int r0 = warp * 16 + g;

    float c[8][4];
    #pragma unroll
    for (int nt = 0; nt < 8; nt++) { c[nt][0] = c[nt][1] = c[nt][2] = c[nt][3] = 0.f; }

    #pragma unroll
    for (int s = 0; s < 4; s++) {
        int pb = s * 8 + t4;
        uint32_t a0 = sA[r0 * ASTE + pb],       a1 = sA[(r0 + 8) * ASTE + pb];
        uint32_t a2 = sA[r0 * ASTE + pb + 4],   a3 = sA[(r0 + 8) * ASTE + pb + 4];
        #pragma unroll
        for (int nt = 0; nt < 8; nt++) {
            int wc = nt * 8 + g;
            uint32_t bh0 = sWh[pb * WST + wc], bh1 = sWh[(pb + 4) * WST + wc];
            uint32_t bl0 = sWl[pb * WST + wc], bl1 = sWl[(pb + 4) * WST + wc];
            mma16816(c[nt], a0, a1, a2, a3, bh0, bh1);
            mma16816(c[nt], a0, a1, a2, a3, bl0, bl1);
        }
    }

    // epilogue: h = acc + b2 (no activation)
    __half* outb = (gbase < N_LIT) ? (hl16 + gbase * CH) : (hc16 + (gbase - N_LIT) * CH);
    __half2* h16r0 = (__half2*)(outb + (size_t)r0 * CH);
    __half2* h16r1 = (__half2*)(outb + (size_t)(r0 + 8) * CH);
    #pragma unroll
    for (int nt = 0; nt < 8; nt++) {
        int col = nt * 8 + 2 * t4;
        float b0 = sb[col], b1v = sb[col + 1];
        h16r0[col >> 1] = __floats2half2_rn(c[nt][0] + b0, c[nt][1] + b1v);
        h16r1[col >> 1] = __floats2half2_rn(c[nt][2] + b0, c[nt][3] + b1v);
    }
}

// ---------------- 2) single-pass scan (decoupled lookback, ticket-ordered) ----------------
__global__ void __launch_bounds__(SCAN_B) scan_onepass(
    const int* __restrict__ cnt, int* __restrict__ rs, int* __restrict__ cur,
    float* __restrict__ inv, int n)
{
    __shared__ int s[SCAN_B];
    __shared__ int sbid;
    __shared__ int sbase;
    if (threadIdx.x == 0) sbid = (int)atomicAdd(&g_ctr, 1u);
    __syncthreads();
    int bid = sbid;
    int i = bid * SCAN_B + threadIdx.x;
    int v = (i < n) ? cnt[i] : 0;
    s[threadIdx.x] = v;
    __syncthreads();
    for (int off = 1; off < SCAN_B; off <<= 1) {
        int t = (threadIdx.x >= off) ? s[threadIdx.x - off] : 0;
        __syncthreads();
        s[threadIdx.x] += t;
        __syncthreads();
    }
    if (threadIdx.x == 0) {
        int total = s[SCAN_B - 1];
        if (bid == 0) {
            atomicExch(&g_tiles[0], (2ull << 32) | (unsigned)total);
            sbase = 0;
        } else {
            atomicExch(&g_tiles[bid], (1ull << 32) | (unsigned)total);
            int base = 0;
            int t = bid - 1;
            while (t >= 0) {
                u64 st;
                do { st = atomicAdd(&g_tiles[t], 0ull); } while ((st >> 32) == 0ull);
                base += (int)(unsigned)st;
                if ((st >> 32) == 2ull) break;
                t--;
            }
            atomicExch(&g_tiles[bid], (2ull << 32) | (unsigned)(base + total));
            sbase = base;
        }
    }
    __syncthreads();
    int base = sbase;
    if (i < n) {
        int r = base + s[threadIdx.x] - v;
        rs[i] = r;
        cur[i] = r;
        inv[i] = (v > 0) ? (1.0f / (float)v) : 1.0f;
    }
    if (bid == 0 && threadIdx.x == 0) rs[n] = 2 * NE;
}

// ---------------- 3) adjacency fill (+ reset cnt / scan state for next call) ----------------
__global__ void fill_kernel(const int* __restrict__ el, const int* __restrict__ ec,
                            int* __restrict__ cur, int* __restrict__ adj,
                            int* __restrict__ cnt) {
    int e = blockIdx.x * 256 + threadIdx.x;
    if (e < NT) cnt[e] = 0;
    if (e < 1024) g_tiles[e] = 0ull;
    if (e == 0) g_ctr = 0u;
    if (e < NE) {
        int l = __ldg(el + e), c = __ldg(ec + e);
        adj[atomicAdd(cur + c, 1)]         = l;
        adj[atomicAdd(cur + N_CLS + l, 1)] = c;
    }
}

// ---------------- aggregation: warp-per-node, fp16 source + fp16 dest ----------------
__global__ void __launch_bounds__(256) agg_kernel(
    const __half* __restrict__ src, const int* __restrict__ rs,
    const int* __restrict__ adj, const float* __restrict__ inv,
    __half* __restrict__ m, int n)
{
    int w = (blockIdx.x * 256 + threadIdx.x) >> 5;
    if (w >= n) return;
    int lane = threadIdx.x & 31;
    u64 pol = make_policy_evict_last();
    int start = __ldg(rs + w), end = __ldg(rs + w + 1);
    const uint32_t* base = (const uint32_t*)src;
    float ax = 0.f, ay = 0.f;
    for (int p0 = start; p0 < end; p0 += 4) {
        int r = end - p0;
        int j0 = __ldg(adj + p0);
        int j1 = (r > 1) ? __ldg(adj + p0 + 1) : j0;
        int j2 = (r > 2) ? __ldg(adj + p0 + 2) : j0;
        int j3 = (r > 3) ? __ldg(adj + p0 + 3) : j0;
        uint32_t u0 = ldg_hint_u32(base + (size_t)j0 * 32 + lane, pol);
        uint32_t u1 = ldg_hint_u32(base + (size_t)j1 * 32 + lane, pol);
        uint32_t u2 = ldg_hint_u32(base + (size_t)j2 * 32 + lane, pol);
        uint32_t u3 = ldg_hint_u32(base + (size_t)j3 * 32 + lane, pol);
        float2 v0 = h2f2(u0), v1 = h2f2(u1), v2 = h2f2(u2), v3 = h2f2(u3);
        float m1 = (r > 1) ? 1.f : 0.f;
        float m2 = (r > 2) ? 1.f : 0.f;
        float m3 = (r > 3) ? 1.f : 0.f;
        ax += v0.x + m1 * v1.x + m2 * v2.x + m3 * v3.x;
        ay += v0.y + m1 * v1.y + m2 * v2.y + m3 * v3.y;
    }
    float iv = __ldg(inv + w);
    __half2 o = __floats2half2_rn(ax * iv, ay * iv);
    stg_cs_u32((uint32_t*)m + (size_t)w * 32 + lane, *(uint32_t*)&o);
}

// ================= f16 HMMA update kernels (pre-split W) =================
#define AST 68

// ---- cls: hc16 = silu([hc16, m16] @ Wc + bc), K=128, in place ----
__global__ void __launch_bounds__(128) cls_update(
    __half* __restrict__ hc16, const __half* __restrict__ m16,
    const uint32_t* __restrict__ wsplit, const float* __restrict__ b)
{
    extern __shared__ uint32_t smu[];
    uint32_t* sA  = smu;                   // [64][68]
    uint32_t* sWh = sA + 64 * AST;         // [64][72]
    uint32_t* sWl = sWh + 64 * WST;
    float*    sb  = (float*)(sWl + 64 * WST);

    int tid = threadIdx.x;
    size_t gbase = (size_t)blockIdx.x * 64;

    // stage pre-split W: 2048 uint4 (hi 1024, lo 1024)
    {
        const uint4* ws = (const uint4*)wsplit;
        for (int idx = tid; idx < 2048; idx += 128) {
            int half = idx >> 10;
            int q = idx & 1023;
            int p = q >> 4, w4 = q & 15;
            uint32_t* dst = half ? sWl : sWh;
            ((uint4*)(dst + p * WST))[w4] = ws[idx];
        }
    }
    const uint32_t* hcu = (const uint32_t*)hc16;
    const uint32_t* mu  = (const uint32_t*)m16;
    for (int idx = tid; idx < 64 * 32; idx += 128) {
        int nd = idx >> 5, pj = idx & 31;
        sA[nd * AST + pj]      = __ldg(hcu + (gbase + nd) * 32 + pj);
        sA[nd * AST + 32 + pj] = ldg_cs_u32(mu + (gbase + nd) * 32 + pj);
    }
    if (tid < 64) sb[tid] = b[tid];
    __syncthreads();

    int lane = tid & 31, warp = tid >> 5;
    int g = lane >> 2, t4 = lane & 3;
    int r0 = warp * 16 + g;

    float c[8][4];
    #pragma unroll
    for (int nt = 0; nt < 8; nt++) { c[nt][0] = c[nt][1] = c[nt][2] = c[nt][3] = 0.f; }

    #pragma unroll
    for (int s = 0; s < 8; s++) {
        int pb = s * 8 + t4;
        uint32_t a0 = sA[r0 * AST + pb],       a1 = sA[(r0 + 8) * AST + pb];
        uint32_t a2 = sA[r0 * AST + pb + 4],   a3 = sA[(r0 + 8) * AST + pb + 4];
        #pragma unroll
        for (int nt = 0; nt < 8; nt++) {
            int wc = nt * 8 + g;
            uint32_t bh0 = sWh[pb * WST + wc], bh1 = sWh[(pb + 4) * WST + wc];
            uint32_t bl0 = sWl[pb * WST + wc], bl1 = sWl[(pb + 4) * WST + wc];
            mma16816(c[nt], a0, a1, a2, a3, bh0, bh1);
            mma16816(c[nt], a0, a1, a2, a3, bl0, bl1);
        }
    }

    size_t row0 = gbase + r0, row1 = row0 + 8;
    __half2* h16r0 = (__half2*)(hc16 + row0 * CH);
    __half2* h16r1 = (__half2*)(hc16 + row1 * CH);
    #pragma unroll
    for (int nt = 0; nt < 8; nt++) {
        int col = nt * 8 + 2 * t4;
        float b0 = sb[col], b1 = sb[col + 1];
        h16r0[col >> 1] = __floats2half2_rn(silu(c[nt][0] + b0), silu(c[nt][1] + b1));
        h16r1[col >> 1] = __floats2half2_rn(silu(c[nt][2] + b0), silu(c[nt][3] + b1));
    }
}

// ---- lit: hdst16 = silu([hsrc16, m16, hsrc16_flip] @ Wl + bl), K=192 ----
__global__ void __launch_bounds__(128) lit_update(
    const __half* __restrict__ hsrc16, __half* __restrict__ hdst16,
    const __half* __restrict__ m16,
    const uint32_t* __restrict__ wsplit, const float* __restrict__ b)
{
    extern __shared__ uint32_t smu[];
    uint32_t* sA  = smu;                   // [64][68]
    uint32_t* sWh = sA + 64 * AST;         // [96][72]
    uint32_t* sWl = sWh + 96 * WST;
    float*    sb  = (float*)(sWl + 96 * WST);

    int tid = threadIdx.x;
    size_t gbase = (size_t)blockIdx.x * 64;

    // stage pre-split W: 3072 uint4 (hi 1536, lo 1536)
    {
        const uint4* ws = (const uint4*)wsplit;
        for (int idx = tid; idx < 3072; idx += 128) {
            int half = (idx >= 1536) ? 1 : 0;
            int q = half ? (idx - 1536) : idx;
            int p = q >> 4, w4 = q & 15;
            uint32_t* dst = half ? sWl : sWh;
            ((uint4*)(dst + p * WST))[w4] = ws[idx];
        }
    }
    const uint32_t* hsu = (const uint32_t*)hsrc16;
    const uint32_t* mu  = (const uint32_t*)m16;
    for (int idx = tid; idx < 64 * 32; idx += 128) {
        int nd = idx >> 5, pj = idx & 31;
        sA[nd * AST + pj]      = __ldg(hsu + (gbase + nd) * 32 + pj);
        sA[nd * AST + 32 + pj] = ldg_cs_u32(mu + (gbase + nd) * 32 + pj);
    }
    if (tid < 64) sb[tid] = b[tid];
    __syncthreads();

    int lane = tid & 31, warp = tid >> 5;
    int g = lane >> 2, t4 = lane & 3;
    int r0 = warp * 16 + g;

    float c[8][4];
    #pragma unroll
    for (int nt = 0; nt < 8; nt++) { c[nt][0] = c[nt][1] = c[nt][2] = c[nt][3] = 0.f; }

    // segments 1+2: self + m (A pairs 0..63, W pairs 0..63)
    #pragma unroll
    for (int s = 0; s < 8; s++) {
        int pb = s * 8 + t4;
        uint32_t a0 = sA[r0 * AST + pb],       a1 = sA[(r0 + 8) * AST + pb];
        uint32_t a2 = sA[r0 * AST + pb + 4],   a3 = sA[(r0 + 8) * AST + pb + 4];
        #pragma unroll
        for (int nt = 0; nt < 8; nt++) {
            int wc = nt * 8 + g;
            uint32_t bh0 = sWh[pb * WST + wc], bh1 = sWh[(pb + 4) * WST + wc];
            uint32_t bl0 = sWl[pb * WST + wc], bl1 = sWl[(pb + 4) * WST + wc];
            mma16816(c[nt], a0, a1, a2, a3, bh0, bh1);
            mma16816(c[nt], a0, a1, a2, a3, bl0, bl1);
        }
    }
    // segment 3: flip (A = self of node^1, pairs 0..31; W pairs 64..95)
    int f0 = r0 ^ 1, f1 = (r0 + 8) ^ 1;
    #pragma unroll
    for (int s = 0; s < 4; s++) {
        int pa = s * 8 + t4;
        int pw = 64 + s * 8 + t4;
        uint32_t a0 = sA[f0 * AST + pa],       a1 = sA[f1 * AST + pa];
        uint32_t a2 = sA[f0 * AST + pa + 4],   a3 = sA[f1 * AST + pa + 4];
        #pragma unroll
        for (int nt = 0; nt < 8; nt++) {
            int wc = nt * 8 + g;
            uint32_t bh0 = sWh[pw * WST + wc], bh1 = sWh[(pw + 4) * WST + wc];
            uint32_t bl0 = sWl[pw * WST + wc], bl1 = sWl[(pw + 4) * WST + wc];
            mma16816(c[nt], a0, a1, a2, a3, bh0, bh1);
            mma16816(c[nt], a0, a1, a2, a3, bl0, bl1);
        }
    }

    size_t row0 = gbase + r0, row1 = row0 + 8;
    __half2* h16r0 = (__half2*)(hdst16 + row0 * CH);
    __half2* h16r1 = (__half2*)(hdst16 + row1 * CH);
    #pragma unroll
    for (int nt = 0; nt < 8; nt++) {
        int col = nt * 8 + 2 * t4;
        float b0 = sb[col], b1 = sb[col + 1];
        h16r0[col >> 1] = __floats2half2_rn(silu(c[nt][0] + b0), silu(c[nt][1] + b1));
        h16r1[col >> 1] = __floats2half2_rn(silu(c[nt][2] + b0), silu(c[nt][3] + b1));
    }
}

// ---------------- readout (fp16 input, fp32 math) ----------------
#define W1T_STRIDE 132
__global__ void __launch_bounds__(128) readout_kernel(
    const __half* __restrict__ hl16,
    const float* __restrict__ w1, const float* __restrict__ b1,
    const float* __restrict__ w2, const float* __restrict__ b2,
    float* __restrict__ out)
{
    extern __shared__ __align__(16) float smem[];
    float* sW1T = smem;
    float* sb1  = smem + 128 * W1T_STRIDE;
    float* sW2  = sb1 + 128;
    float* sb2  = sW2 + 256;
    for (int t = threadIdx.x; t < 128 * 128; t += 128) {
        int i = t >> 7, k = t & 127;
        sW1T[k * W1T_STRIDE + i] = w1[t];
    }
    sb1[threadIdx.x] = b1[threadIdx.x];
    for (int t = threadIdx.x; t < 256; t += 128) sW2[t] = w2[t];
    if (threadIdx.x < 2) sb2[threadIdx.x] = b2[threadIdx.x];
    __syncthreads();
    uint32_t swa = (uint32_t)__cvta_generic_to_shared(sW1T);

    int v = blockIdx.x * 128 + threadIdx.x;
    if (v >= NVAR) return;

    u64 hv2[64];
    const uint32_t* hp = (const uint32_t*)(hl16 + (size_t)v * 128);
    #pragma unroll
    for (int j = 0; j < 64; j++) {
        float2 f = h2f2(__ldg(hp + j));
        hv2[j] = pack2(f.x, f.y);
    }

    float y0 = sb2[0], y1 = sb2[1];
    #pragma unroll 2
    for (int k = 0; k < 128; k++) {
        u64 t0 = 0, t1 = 0, t2 = 0, t3 = 0;
        uint32_t ra = swa + k * (W1T_STRIDE * 4);
        #pragma unroll
        for (int j = 0; j < 32; j++) {
            u64 w0, w1v;
            lds_v2u64(w0, w1v, ra + (j << 4));
            fma2((j & 1) ? t1 : t0, hv2[2 * j],     w0);
            fma2((j & 1) ? t3 : t2, hv2[2 * j + 1], w1v);
        }
        float2 a = unpack2(t0), bq = unpack2(t1), c = unpack2(t2), d = unpack2(t3);
        float t = ((a.x + a.y) + (bq.x + bq.y)) + ((c.x + c.y) + (d.x + d.y)) + sb1[k];
        float s = silu(t);
        y0 += s * sW2[2 * k];
        y1 += s * sW2[2 * k + 1];
    }
    out[2 * v]     = y0;
    out[2 * v + 1] = y1;
}

// ---------------- launcher ----------------
extern "C" void kernel_launch(void* const* d_in, const int* in_sizes, int n_in,
                              void* d_out, int out_size)
{
    const float* x_lit  = (const float*)d_in[0];
    const float* x_cls  = (const float*)d_in[1];
    const int*   e_lit  = (const int*)  d_in[2];
    const int*   e_cls  = (const int*)  d_in[3];
    const float* enc_w1 = (const float*)d_in[4];
    const float* enc_b1 = (const float*)d_in[5];
    const float* enc_w2 = (const float*)d_in[6];
    const float* enc_b2 = (const float*)d_in[7];
    const float* Wc     = (const float*)d_in[8];
    const float* bc     = (const float*)d_in[9];
    const float* Wl     = (const float*)d_in[10];
    const float* bl     = (const float*)d_in[11];
    const float* out_w1 = (const float*)d_in[12];
    const float* out_b1 = (const float*)d_in[13];
    const float* out_w2 = (const float*)d_in[14];
    const float* out_b2 = (const float*)d_in[15];
    float* y = (float*)d_out;

    __half *p_hlA16, *p_hlB16, *p_hc16, *p_m16;
    float *p_inv;
    int *p_cnt, *p_rs, *p_cur, *p_adj;
    uint32_t *p_wcls, *p_wlit;
    cudaGetSymbolAddress((void**)&p_hlA16, g_hlA16);
    cudaGetSymbolAddress((void**)&p_hlB16, g_hlB16);
    cudaGetSymbolAddress((void**)&p_hc16,  g_hc16);
    cudaGetSymbolAddress((void**)&p_m16,   g_m16);
    cudaGetSymbolAddress((void**)&p_cnt, g_cnt);
    cudaGetSymbolAddress((void**)&p_inv, g_inv);
    cudaGetSymbolAddress((void**)&p_rs,  g_rs);
    cudaGetSymbolAddress((void**)&p_cur, g_cur);
    cudaGetSymbolAddress((void**)&p_adj, g_adj);
    cudaGetSymbolAddress((void**)&p_wcls, g_wcls16);
    cudaGetSymbolAddress((void**)&p_wlit, g_wlit16);

    const int smem_enc = (64 * ASTE + 2 * 32 * WST) * 4 + (4 * CH + 2 * CH) * 4;  // ~29.2 KB
    const int smem_cls = (64 * AST + 2 * 64 * WST + 64) * 4;                      // 54,528 B
    const int smem_lit = (64 * AST + 2 * 96 * WST + 64) * 4;                      // 72,960 B
    cudaFuncSetAttribute(encoder_kernel, cudaFuncAttributeMaxDynamicSharedMemorySize, smem_enc);
    cudaFuncSetAttribute(cls_update, cudaFuncAttributeMaxDynamicSharedMemorySize, smem_cls);
    cudaFuncSetAttribute(lit_update, cudaFuncAttributeMaxDynamicSharedMemorySize, smem_lit);
    cudaFuncSetAttribute(readout_kernel, cudaFuncAttributeMaxDynamicSharedMemorySize,
                         (128 * W1T_STRIDE + 128 + 256 + 8) * 4);

    // 0) pre-split all weights (43008 entries)
    prep_weights<<<168, 256>>>(enc_w2, Wc, Wl);

    // 1) encoder (HMMA) + edge counting; NT = 64 * 15625
    encoder_kernel<<<NT / 64, 128, smem_enc>>>(
        x_lit, x_cls, enc_w1, enc_b1, enc_b2,
        e_lit, e_cls, p_cnt, p_hlA16, p_hc16);

    // 2) single-pass scan -> rs, cur, inv
    int nb = (NT + SCAN_B - 1) / SCAN_B;
    scan_onepass<<<nb, SCAN_B>>>(p_cnt, p_rs, p_cur, p_inv, NT);

    // 3) adjacency fill + reset cnt/scan state
    fill_kernel<<<(NE + 255) / 256, 256>>>(e_lit, e_cls, p_cur, p_adj, p_cnt);

    // 4+) message-passing layers (all state fp16, pre-split W)
    __half* cur16 = p_hlA16;
    __half* nxt16 = p_hlB16;
    for (int l = 0; l < NLAY; l++) {
        agg_kernel<<<((size_t)N_CLS * 32 + 255) / 256, 256>>>(
            cur16, p_rs, p_adj, p_inv, p_m16, N_CLS);
        cls_update<<<N_CLS / 64, 128, smem_cls>>>(
            p_hc16, p_m16, p_wcls + (size_t)l * 8192, bc + l * CH);
        agg_kernel<<<((size_t)N_LIT * 32 + 255) / 256, 256>>>(
            p_hc16, p_rs + N_CLS, p_adj, p_inv + N_CLS, p_m16, N_LIT);
        lit_update<<<N_LIT / 64, 128, smem_lit>>>(
            cur16, nxt16, p_m16, p_wlit + (size_t)l * 12288, bl + l * CH);
        __half* tmp = cur16; cur16 = nxt16; nxt16 = tmp;
    }

    // readout
    readout_kernel<<<(NVAR + 127) / 128, 128, (128 * W1T_STRIDE + 128 + 256 + 8) * 4>>>(
        cur16, out_w1, out_b1, out_w2, out_b2, y);
}